// round 9
// baseline (speedup 1.0000x reference)
#include <cuda_runtime.h>
#include <cuda_bf16.h>

#define N_NODES   10000
#define N_EDGES   160000
#define E_TOT     170000
#define D_MODEL   128
#define NHEAD     8
#define HEAD_DIM  16
#define NUM_LAYERS 7
#define CHUNK     10
#define NUM_LABELS 2
#define NEG_SLOPE 0.2f

// ---------------- device scratch ----------------
__device__ float g_bufA[N_NODES * D_MODEL];
__device__ float g_bufB[N_NODES * D_MODEL];
__device__ float g_xl[N_NODES * D_MODEL];
__device__ float g_xr[N_NODES * D_MODEL];
__device__ int   g_src[E_TOT];
__device__ int   g_dst[E_TOT];
__device__ int   g_cnt[N_NODES];
__device__ int   g_start[N_NODES + 1];
__device__ int   g_cursor[N_NODES];
__device__ int   g_csr[E_TOT];
__device__ int   g_is64;

// ---------------- packed f32x2 helpers ----------------
__device__ __forceinline__ void ffma2(unsigned long long& d,
                                      unsigned long long a,
                                      unsigned long long b) {
    asm("fma.rn.f32x2 %0, %1, %2, %0;" : "+l"(d) : "l"(a), "l"(b));
}
__device__ __forceinline__ unsigned long long addf32x2(unsigned long long a,
                                                       unsigned long long b) {
    unsigned long long r;
    asm("add.rn.f32x2 %0, %1, %2;" : "=l"(r) : "l"(a), "l"(b));
    return r;
}
__device__ __forceinline__ unsigned long long dup2(float x) {
    unsigned long long r;
    asm("mov.b64 %0, {%1, %1};" : "=l"(r) : "f"(x));
    return r;
}

// ---------------- cp.async helpers ----------------
__device__ __forceinline__ unsigned smem_u32(const void* p) {
    unsigned a;
    asm("{ .reg .u64 t; cvta.to.shared.u64 t, %1; cvt.u32.u64 %0, t; }"
        : "=r"(a) : "l"(p));
    return a;
}
__device__ __forceinline__ void cp16(unsigned s, const void* g) {
    asm volatile("cp.async.ca.shared.global [%0], [%1], 16;" :: "r"(s), "l"(g));
}
#define CP_COMMIT() asm volatile("cp.async.commit_group;")

// ------------- dtype detect (int32 vs int64) + zero counters -------------
__global__ void k_detect_zero(const int* __restrict__ e32) {
    int t = blockIdx.x * blockDim.x + threadIdx.x;
    if (t < N_NODES) g_cnt[t] = 0;
    if (blockIdx.x == 0) {
        __shared__ int nz;
        if (threadIdx.x == 0) nz = 0;
        __syncthreads();
        for (int i = threadIdx.x; i < 1024; i += blockDim.x)
            if (e32[2 * i + 1] != 0) nz = 1;
        __syncthreads();
        if (threadIdx.x == 0) g_is64 = (nz == 0) ? 1 : 0;
    }
}

__global__ void k_extract(const int* __restrict__ e32) {
    int t = blockIdx.x * blockDim.x + threadIdx.x;
    if (t >= E_TOT) return;
    int s, d;
    if (t < N_EDGES) {
        if (g_is64) { s = e32[2 * t]; d = e32[2 * (N_EDGES + t)]; }
        else        { s = e32[t];     d = e32[N_EDGES + t]; }
    } else {
        s = t - N_EDGES; d = s;
    }
    g_src[t] = s;
    g_dst[t] = d;
    atomicAdd(&g_cnt[d], 1);
}

// exclusive scan of g_cnt. one block, 1024 threads, warp-shuffle two-level.
__global__ void __launch_bounds__(1024) k_scan() {
    __shared__ int warpsum[32];
    const int t    = threadIdx.x;
    const int lane = t & 31;
    const int warp = t >> 5;
    const int base = t * 10;

    int local[10];
    int sum = 0;
    #pragma unroll
    for (int i = 0; i < 10; i++) {
        int idx = base + i;
        local[i] = (idx < N_NODES) ? g_cnt[idx] : 0;
        sum += local[i];
    }
    int incl = sum;
    #pragma unroll
    for (int off = 1; off < 32; off <<= 1) {
        int v = __shfl_up_sync(0xffffffffu, incl, off);
        if (lane >= off) incl += v;
    }
    if (lane == 31) warpsum[warp] = incl;
    __syncthreads();
    if (warp == 0) {
        int w = warpsum[lane];
        int wi = w;
        #pragma unroll
        for (int off = 1; off < 32; off <<= 1) {
            int v = __shfl_up_sync(0xffffffffu, wi, off);
            if (lane >= off) wi += v;
        }
        warpsum[lane] = wi - w;
    }
    __syncthreads();
    int run = warpsum[warp] + (incl - sum);
    #pragma unroll
    for (int i = 0; i < 10; i++) {
        int idx = base + i;
        if (idx < N_NODES) {
            g_start[idx]  = run;
            g_cursor[idx] = run;
        }
        run += local[i];
    }
    if (t == 0) g_start[N_NODES] = E_TOT;
}

__global__ void k_scatter() {
    int t = blockIdx.x * blockDim.x + threadIdx.x;
    if (t >= E_TOT) return;
    int d = g_dst[t];
    int pos = atomicAdd(&g_cursor[d], 1);
    g_csr[pos] = g_src[t];
}

// ---------------- fused GEMM: xl = X@Wl + bl ; xr = X@Wr + br -------------
// 32x128 tile, 128 threads, 4x8 FFMA2 micro-tile.
// A: LDG (overlapped) -> duplicated f32x2 in smem, transposed [k][row].
// B: cp.async double-buffered.
// __launch_bounds__(128,6): <=85 regs -> 6 blocks/SM -> grid 626 fully resident.
__global__ void __launch_bounds__(128, 6) k_gemm(
    const float* __restrict__ X,
    const float* __restrict__ Wl, const float* __restrict__ bl,
    const float* __restrict__ Wr, const float* __restrict__ br)
{
    const float* W = blockIdx.y ? Wr : Wl;
    const float* b = blockIdx.y ? br : bl;
    float* out = blockIdx.y ? g_xr : g_xl;

    __shared__ unsigned long long As2[2][16][34];  // {a,a} pairs, [k][row], padded
    __shared__ float Bs[2][16][128];

    const int tid  = threadIdx.x;
    const int tx   = tid & 15;         // col group: 8 cols at tx*8
    const int ty   = tid >> 4;         // row group: 4 rows at ty*4
    const int row0 = blockIdx.x * 32;

    // A: one float4 per thread per k-tile
    const int a_r  = tid >> 2;                 // 0..31
    const int a_c4 = (tid & 3) * 4;            // 0,4,8,12
    int a_gr = row0 + a_r;
    if (a_gr >= N_NODES) a_gr = N_NODES - 1;   // clamp; garbage rows unstored
    const float* a_src = X + a_gr * 128 + a_c4;

    // B: 512 float4 per k-tile, 4 per thread
    const int b_r  = tid >> 5;                 // 0..3 (+strides of 4)
    const int b_c4 = (tid & 31) * 4;

    unsigned long long acc2[4][4];
    #pragma unroll
    for (int i = 0; i < 4; i++)
        #pragma unroll
        for (int j = 0; j < 4; j++) acc2[i][j] = 0ull;

    // prefetch: A tile 0 into regs, B tile 0 via cp.async
    float4 areg = *(const float4*)(a_src);
    #pragma unroll
    for (int f = 0; f < 4; f++)
        cp16(smem_u32(&Bs[0][b_r + f * 4][b_c4]), W + (b_r + f * 4) * 128 + b_c4);
    CP_COMMIT();

    #pragma unroll
    for (int t = 0; t < 8; t++) {
        const int cur = t & 1;

        // stage A tile t (duplicated pairs, transposed)
        As2[cur][a_c4 + 0][a_r] = dup2(areg.x);
        As2[cur][a_c4 + 1][a_r] = dup2(areg.y);
        As2[cur][a_c4 + 2][a_r] = dup2(areg.z);
        As2[cur][a_c4 + 3][a_r] = dup2(areg.w);

        if (t < 7) {
            const int nb = cur ^ 1;
            const int k1 = (t + 1) * 16;
            areg = *(const float4*)(a_src + k1);          // overlap LDG
            #pragma unroll
            for (int f = 0; f < 4; f++)
                cp16(smem_u32(&Bs[nb][b_r + f * 4][b_c4]),
                     W + (k1 + b_r + f * 4) * 128 + b_c4);
            CP_COMMIT();
            asm volatile("cp.async.wait_group 1;");       // B tile t ready
        } else {
            asm volatile("cp.async.wait_group 0;");
        }
        __syncthreads();

        #pragma unroll
        for (int k = 0; k < 16; k++) {
            ulonglong2 a01 = *(const ulonglong2*)(&As2[cur][k][ty * 4 + 0]);
            ulonglong2 a23 = *(const ulonglong2*)(&As2[cur][k][ty * 4 + 2]);
            ulonglong2 p01 = *(const ulonglong2*)(&Bs[cur][k][tx * 8 + 0]);
            ulonglong2 p23 = *(const ulonglong2*)(&Bs[cur][k][tx * 8 + 4]);
            ffma2(acc2[0][0], a01.x, p01.x); ffma2(acc2[0][1], a01.x, p01.y);
            ffma2(acc2[0][2], a01.x, p23.x); ffma2(acc2[0][3], a01.x, p23.y);
            ffma2(acc2[1][0], a01.y, p01.x); ffma2(acc2[1][1], a01.y, p01.y);
            ffma2(acc2[1][2], a01.y, p23.x); ffma2(acc2[1][3], a01.y, p23.y);
            ffma2(acc2[2][0], a23.x, p01.x); ffma2(acc2[2][1], a23.x, p01.y);
            ffma2(acc2[2][2], a23.x, p23.x); ffma2(acc2[2][3], a23.x, p23.y);
            ffma2(acc2[3][0], a23.y, p01.x); ffma2(acc2[3][1], a23.y, p01.y);
            ffma2(acc2[3][2], a23.y, p23.x); ffma2(acc2[3][3], a23.y, p23.y);
        }
        __syncthreads();
    }

    const int cc = tx * 8;
    ulonglong2 bp01 = *(const ulonglong2*)(b + cc);
    ulonglong2 bp23 = *(const ulonglong2*)(b + cc + 4);
    #pragma unroll
    for (int i = 0; i < 4; i++) {
        int gr = row0 + ty * 4 + i;
        if (gr < N_NODES) {
            ulonglong2 o0, o1;
            o0.x = addf32x2(acc2[i][0], bp01.x);
            o0.y = addf32x2(acc2[i][1], bp01.y);
            o1.x = addf32x2(acc2[i][2], bp23.x);
            o1.y = addf32x2(acc2[i][3], bp23.y);
            *(ulonglong2*)(out + gr * 128 + cc + 0) = o0;
            *(ulonglong2*)(out + gr * 128 + cc + 4) = o1;
        }
    }
}

// ---------------- fused edge kernel: NO-MAX softmax + aggregate ----------
// Softmax is shift-invariant and e = att.leakyrelu(...) is O(1) here, so
// exp(e) directly is safe in fp32 — no serial online-max chain.
__global__ void __launch_bounds__(256) k_layer(
    const float* __restrict__ att, const float* __restrict__ bias,
    float* __restrict__ out)
{
    const int warp = threadIdx.x >> 5;
    const int n    = blockIdx.x * 8 + warp;
    if (n >= N_NODES) return;
    const int lane = threadIdx.x & 31;
    const int c    = lane * 4;

    const float4 xr = *(const float4*)(g_xr + n * 128 + c);
    const float4 av = *(const float4*)(att + c);

    const int beg = g_start[n];
    const int end = g_start[n + 1];   // >= beg+1 (self loop)

    float  s = 0.0f;
    float4 acc = make_float4(0.f, 0.f, 0.f, 0.f);

    float4 v0 = *(const float4*)(g_xl + g_csr[beg] * 128 + c);
    float4 v1 = (beg + 1 < end)
        ? *(const float4*)(g_xl + g_csr[beg + 1] * 128 + c) : v0;

    for (int e = beg; e < end; e++) {
        float4 cur = v0;
        v0 = v1;
        if (e + 2 < end)
            v1 = *(const float4*)(g_xl + g_csr[e + 2] * 128 + c);

        float zx = cur.x + xr.x; zx = fmaxf(zx, NEG_SLOPE * zx);
        float zy = cur.y + xr.y; zy = fmaxf(zy, NEG_SLOPE * zy);
        float zz = cur.z + xr.z; zz = fmaxf(zz, NEG_SLOPE * zz);
        float zw = cur.w + xr.w; zw = fmaxf(zw, NEG_SLOPE * zw);
        float w = zx * av.x;
        w = fmaf(zy, av.y, w);
        w = fmaf(zz, av.z, w);
        w = fmaf(zw, av.w, w);
        w += __shfl_xor_sync(0xffffffffu, w, 1);
        w += __shfl_xor_sync(0xffffffffu, w, 2);

        float p = __expf(w);
        s += p;
        acc.x = fmaf(p, cur.x, acc.x);
        acc.y = fmaf(p, cur.y, acc.y);
        acc.z = fmaf(p, cur.z, acc.z);
        acc.w = fmaf(p, cur.w, acc.w);
    }

    const float inv = 1.0f / (s + 1e-16f);
    const float4 bi = *(const float4*)(bias + c);
    float4 o;
    o.x = acc.x * inv + bi.x;
    o.y = acc.y * inv + bi.y;
    o.z = acc.z * inv + bi.z;
    o.w = acc.w * inv + bi.w;
    *(float4*)(out + n * 128 + c) = o;
}

// ---------------- final head ----------------
__global__ void k_head(const float* __restrict__ xin, const float* __restrict__ w,
                       const float* __restrict__ bh, float* __restrict__ out)
{
    int gt   = blockIdx.x * blockDim.x + threadIdx.x;
    int warp = gt >> 5;
    int lane = gt & 31;
    if (warp >= (N_NODES / CHUNK) * NUM_LABELS) return;
    int c = warp / NUM_LABELS;
    int l = warp % NUM_LABELS;
    const float* row = xin + (c * CHUNK + l) * 128;
    float s = 0.0f;
    #pragma unroll
    for (int i = lane; i < 128; i += 32) s = fmaf(row[i], w[i], s);
    #pragma unroll
    for (int o = 16; o; o >>= 1) s += __shfl_down_sync(0xffffffffu, s, o);
    if (lane == 0) out[warp] = s + bh[0];
}

// ---------------- launch ----------------
extern "C" void kernel_launch(void* const* d_in, const int* in_sizes, int n_in,
                              void* d_out, int out_size)
{
    const float* x    = (const float*)d_in[0];
    const int*   eidx = (const int*)  d_in[1];
    // d_in[2] = nchunks (fixed = 8 -> CHUNK = 10)
    const float* Wl   = (const float*)d_in[3];
    const float* bl   = (const float*)d_in[4];
    const float* Wr   = (const float*)d_in[5];
    const float* br   = (const float*)d_in[6];
    const float* att  = (const float*)d_in[7];
    const float* bias = (const float*)d_in[8];
    const float* wh   = (const float*)d_in[9];
    const float* bh   = (const float*)d_in[10];
    float* out = (float*)d_out;

    float *bufA = nullptr, *bufB = nullptr;
    cudaGetSymbolAddress((void**)&bufA, g_bufA);
    cudaGetSymbolAddress((void**)&bufB, g_bufB);

    dim3 gg((N_NODES + 31) / 32, 2);
    const int layer_grid = (N_NODES + 7) / 8;

    // profiled slot #4 = k_gemm
    k_detect_zero<<<(N_NODES + 255) / 256, 256>>>(eidx);   // 1
    k_extract<<<(E_TOT + 255) / 256, 256>>>(eidx);         // 2
    k_scan<<<1, 1024>>>();                                 // 3
    k_gemm<<<gg, 128>>>(x, Wl, bl, Wr, br);                // 4  <-- profiled
    k_scatter<<<(E_TOT + 255) / 256, 256>>>();             // 5
    k_layer<<<layer_grid, 256>>>(att, bias, bufA);         // 6

    const float* cur = bufA;
    for (int l = 1; l < NUM_LAYERS; l++) {
        float* nxt = (l & 1) ? bufB : bufA;
        k_gemm<<<gg, 128>>>(cur,
                            Wl + l * D_MODEL * D_MODEL, bl + l * D_MODEL,
                            Wr + l * D_MODEL * D_MODEL, br + l * D_MODEL);
        k_layer<<<layer_grid, 256>>>(att + l * NHEAD * HEAD_DIM,
                                     bias + l * D_MODEL, nxt);
        cur = nxt;
    }
    int nwarp = (N_NODES / CHUNK) * NUM_LABELS;
    k_head<<<(nwarp * 32 + 255) / 256, 256>>>(cur, wh, bh, out);
}

// round 11
// speedup vs baseline: 1.0756x; 1.0756x over previous
#include <cuda_runtime.h>
#include <cuda_bf16.h>

#define N_NODES   10000
#define N_EDGES   160000
#define E_TOT     170000
#define D_MODEL   128
#define NHEAD     8
#define HEAD_DIM  16
#define NUM_LAYERS 7
#define CHUNK     10
#define NUM_LABELS 2
#define NEG_SLOPE 0.2f

// ---------------- device scratch ----------------
__device__ float g_bufA[N_NODES * D_MODEL];
__device__ float g_bufB[N_NODES * D_MODEL];
__device__ float g_xl[N_NODES * D_MODEL];
__device__ float g_xr[N_NODES * D_MODEL];
__device__ int   g_src[E_TOT];
__device__ int   g_dst[E_TOT];
__device__ int   g_cnt[N_NODES];
__device__ int   g_start[N_NODES + 1];
__device__ int   g_cursor[N_NODES];
__device__ int   g_csr[E_TOT];
__device__ int   g_is64;

// ---------------- packed f32x2 helpers ----------------
__device__ __forceinline__ unsigned long long pack2(float x) {
    unsigned long long r;
    asm("mov.b64 %0, {%1, %1};" : "=l"(r) : "f"(x));
    return r;
}
__device__ __forceinline__ void ffma2(unsigned long long& d,
                                      unsigned long long a,
                                      unsigned long long b) {
    asm("fma.rn.f32x2 %0, %1, %2, %0;" : "+l"(d) : "l"(a), "l"(b));
}
__device__ __forceinline__ unsigned long long addf32x2(unsigned long long a,
                                                       unsigned long long b) {
    unsigned long long r;
    asm("add.rn.f32x2 %0, %1, %2;" : "=l"(r) : "l"(a), "l"(b));
    return r;
}

// ---------------- cp.async helpers ----------------
__device__ __forceinline__ unsigned smem_u32(const void* p) {
    unsigned a;
    asm("{ .reg .u64 t; cvta.to.shared.u64 t, %1; cvt.u32.u64 %0, t; }"
        : "=r"(a) : "l"(p));
    return a;
}
__device__ __forceinline__ void cp16(unsigned s, const void* g) {
    asm volatile("cp.async.ca.shared.global [%0], [%1], 16;" :: "r"(s), "l"(g));
}
#define CP_COMMIT() asm volatile("cp.async.commit_group;")

// ------------- dtype detect (int32 vs int64) + zero counters -------------
__global__ void k_detect_zero(const int* __restrict__ e32) {
    int t = blockIdx.x * blockDim.x + threadIdx.x;
    if (t < N_NODES) g_cnt[t] = 0;
    if (blockIdx.x == 0) {
        __shared__ int nz;
        if (threadIdx.x == 0) nz = 0;
        __syncthreads();
        for (int i = threadIdx.x; i < 1024; i += blockDim.x)
            if (e32[2 * i + 1] != 0) nz = 1;
        __syncthreads();
        if (threadIdx.x == 0) g_is64 = (nz == 0) ? 1 : 0;
    }
}

__global__ void k_extract(const int* __restrict__ e32) {
    int t = blockIdx.x * blockDim.x + threadIdx.x;
    if (t >= E_TOT) return;
    int s, d;
    if (t < N_EDGES) {
        if (g_is64) { s = e32[2 * t]; d = e32[2 * (N_EDGES + t)]; }
        else        { s = e32[t];     d = e32[N_EDGES + t]; }
    } else {
        s = t - N_EDGES; d = s;
    }
    g_src[t] = s;
    g_dst[t] = d;
    atomicAdd(&g_cnt[d], 1);
}

// exclusive scan of g_cnt. one block, 1024 threads, warp-shuffle two-level.
__global__ void __launch_bounds__(1024) k_scan() {
    __shared__ int warpsum[32];
    const int t    = threadIdx.x;
    const int lane = t & 31;
    const int warp = t >> 5;
    const int base = t * 10;

    int local[10];
    int sum = 0;
    #pragma unroll
    for (int i = 0; i < 10; i++) {
        int idx = base + i;
        local[i] = (idx < N_NODES) ? g_cnt[idx] : 0;
        sum += local[i];
    }
    int incl = sum;
    #pragma unroll
    for (int off = 1; off < 32; off <<= 1) {
        int v = __shfl_up_sync(0xffffffffu, incl, off);
        if (lane >= off) incl += v;
    }
    if (lane == 31) warpsum[warp] = incl;
    __syncthreads();
    if (warp == 0) {
        int w = warpsum[lane];
        int wi = w;
        #pragma unroll
        for (int off = 1; off < 32; off <<= 1) {
            int v = __shfl_up_sync(0xffffffffu, wi, off);
            if (lane >= off) wi += v;
        }
        warpsum[lane] = wi - w;
    }
    __syncthreads();
    int run = warpsum[warp] + (incl - sum);
    #pragma unroll
    for (int i = 0; i < 10; i++) {
        int idx = base + i;
        if (idx < N_NODES) {
            g_start[idx]  = run;
            g_cursor[idx] = run;
        }
        run += local[i];
    }
    if (t == 0) g_start[N_NODES] = E_TOT;
}

__global__ void k_scatter() {
    int t = blockIdx.x * blockDim.x + threadIdx.x;
    if (t >= E_TOT) return;
    int d = g_dst[t];
    int pos = atomicAdd(&g_cursor[d], 1);
    g_csr[pos] = g_src[t];
}

// ---------------- fused GEMM: xl = X@Wl + bl ; xr = X@Wr + br -------------
// 128x128 tile, BK=16, 256 threads, 8x8 FFMA2 micro-tile (2 B LDS / FFMA2).
// B: cp.async double-buffered. A: LDG prefetch -> transposed smem staging.
__global__ void __launch_bounds__(256) k_gemm(
    const float* __restrict__ X,
    const float* __restrict__ Wl, const float* __restrict__ bl,
    const float* __restrict__ Wr, const float* __restrict__ br)
{
    const float* W = blockIdx.y ? Wr : Wl;
    const float* b = blockIdx.y ? br : bl;
    float* out = blockIdx.y ? g_xr : g_xl;

    __shared__ float As[2][16][132];   // transposed A tile, padded (16B-aligned)
    __shared__ float Bs[2][16][128];

    const int tid  = threadIdx.x;
    const int tx   = tid & 15;         // cols tx*8
    const int ty   = tid >> 4;         // rows ty*8
    const int row0 = blockIdx.x * 128;

    // A: 512 float4 chunks per k-tile, 2 per thread
    const int a_r0  = tid >> 1;                        // chunk tid      : r=tid>>2
    (void)a_r0;
    const int c0_r  = tid >> 2;                        // chunk = tid
    const int c0_c4 = (tid & 3) * 4;
    const int c1_r  = (tid + 256) >> 2;                // chunk = tid+256
    const int c1_c4 = c0_c4;
    int g_r0 = row0 + c0_r; if (g_r0 >= N_NODES) g_r0 = N_NODES - 1;
    int g_r1 = row0 + c1_r; if (g_r1 >= N_NODES) g_r1 = N_NODES - 1;
    const float* a_src0 = X + g_r0 * 128 + c0_c4;
    const float* a_src1 = X + g_r1 * 128 + c1_c4;

    // B: 512 float4 per k-tile, 2 per thread
    const int b_r0 = tid >> 5;          // 0..7
    const int b_c4 = (tid & 31) * 4;
    const int b_r1 = b_r0 + 8;

    unsigned b_dst0[2], b_dst1[2];
    #pragma unroll
    for (int p = 0; p < 2; p++) {
        b_dst0[p] = smem_u32(&Bs[p][b_r0][b_c4]);
        b_dst1[p] = smem_u32(&Bs[p][b_r1][b_c4]);
    }

    unsigned long long acc2[8][4];
    #pragma unroll
    for (int i = 0; i < 8; i++)
        #pragma unroll
        for (int j = 0; j < 4; j++) acc2[i][j] = 0ull;

    // prefetch tile 0: A into regs, B via cp.async
    float4 ar0 = *(const float4*)(a_src0);
    float4 ar1 = *(const float4*)(a_src1);
    cp16(b_dst0[0], W + b_r0 * 128 + b_c4);
    cp16(b_dst1[0], W + b_r1 * 128 + b_c4);
    CP_COMMIT();

    #pragma unroll
    for (int t = 0; t < 8; t++) {
        const int cur = t & 1;

        // stage A tile t (transposed)
        As[cur][c0_c4 + 0][c0_r] = ar0.x;
        As[cur][c0_c4 + 1][c0_r] = ar0.y;
        As[cur][c0_c4 + 2][c0_r] = ar0.z;
        As[cur][c0_c4 + 3][c0_r] = ar0.w;
        As[cur][c1_c4 + 0][c1_r] = ar1.x;
        As[cur][c1_c4 + 1][c1_r] = ar1.y;
        As[cur][c1_c4 + 2][c1_r] = ar1.z;
        As[cur][c1_c4 + 3][c1_r] = ar1.w;

        if (t < 7) {
            const int nb = cur ^ 1;
            const int k1 = (t + 1) * 16;
            ar0 = *(const float4*)(a_src0 + k1);       // overlap LDG
            ar1 = *(const float4*)(a_src1 + k1);
            cp16(b_dst0[nb], W + (k1 + b_r0) * 128 + b_c4);
            cp16(b_dst1[nb], W + (k1 + b_r1) * 128 + b_c4);
            CP_COMMIT();
            asm volatile("cp.async.wait_group 1;");    // B tile t ready
        } else {
            asm volatile("cp.async.wait_group 0;");
        }
        __syncthreads();

        #pragma unroll
        for (int k = 0; k < 16; k++) {
            float a[8];
            *(float4*)(a + 0) = *(const float4*)(&As[cur][k][ty * 8 + 0]);
            *(float4*)(a + 4) = *(const float4*)(&As[cur][k][ty * 8 + 4]);
            ulonglong2 p01 = *(const ulonglong2*)(&Bs[cur][k][tx * 8 + 0]);
            ulonglong2 p23 = *(const ulonglong2*)(&Bs[cur][k][tx * 8 + 4]);
            #pragma unroll
            for (int i = 0; i < 8; i++) {
                unsigned long long Ai = pack2(a[i]);
                ffma2(acc2[i][0], Ai, p01.x);
                ffma2(acc2[i][1], Ai, p01.y);
                ffma2(acc2[i][2], Ai, p23.x);
                ffma2(acc2[i][3], Ai, p23.y);
            }
        }
        __syncthreads();
    }

    const int cc = tx * 8;
    ulonglong2 bp01 = *(const ulonglong2*)(b + cc);
    ulonglong2 bp23 = *(const ulonglong2*)(b + cc + 4);
    #pragma unroll
    for (int i = 0; i < 8; i++) {
        int gr = row0 + ty * 8 + i;
        if (gr < N_NODES) {
            ulonglong2 o0, o1;
            o0.x = addf32x2(acc2[i][0], bp01.x);
            o0.y = addf32x2(acc2[i][1], bp01.y);
            o1.x = addf32x2(acc2[i][2], bp23.x);
            o1.y = addf32x2(acc2[i][3], bp23.y);
            *(ulonglong2*)(out + gr * 128 + cc + 0) = o0;
            *(ulonglong2*)(out + gr * 128 + cc + 4) = o1;
        }
    }
}

// ---------------- fused edge kernel: NO-MAX softmax + aggregate ----------
// Softmax is shift-invariant and e = att.leakyrelu(...) is O(1) here, so
// exp(e) directly is safe in fp32 — no serial online-max chain.
__global__ void __launch_bounds__(256) k_layer(
    const float* __restrict__ att, const float* __restrict__ bias,
    float* __restrict__ out)
{
    const int warp = threadIdx.x >> 5;
    const int n    = blockIdx.x * 8 + warp;
    if (n >= N_NODES) return;
    const int lane = threadIdx.x & 31;
    const int c    = lane * 4;

    const float4 xr = *(const float4*)(g_xr + n * 128 + c);
    const float4 av = *(const float4*)(att + c);

    const int beg = g_start[n];
    const int end = g_start[n + 1];   // >= beg+1 (self loop)

    float  s = 0.0f;
    float4 acc = make_float4(0.f, 0.f, 0.f, 0.f);

    float4 v0 = *(const float4*)(g_xl + g_csr[beg] * 128 + c);
    float4 v1 = (beg + 1 < end)
        ? *(const float4*)(g_xl + g_csr[beg + 1] * 128 + c) : v0;

    for (int e = beg; e < end; e++) {
        float4 cur = v0;
        v0 = v1;
        if (e + 2 < end)
            v1 = *(const float4*)(g_xl + g_csr[e + 2] * 128 + c);

        float zx = cur.x + xr.x; zx = fmaxf(zx, NEG_SLOPE * zx);
        float zy = cur.y + xr.y; zy = fmaxf(zy, NEG_SLOPE * zy);
        float zz = cur.z + xr.z; zz = fmaxf(zz, NEG_SLOPE * zz);
        float zw = cur.w + xr.w; zw = fmaxf(zw, NEG_SLOPE * zw);
        float w = zx * av.x;
        w = fmaf(zy, av.y, w);
        w = fmaf(zz, av.z, w);
        w = fmaf(zw, av.w, w);
        w += __shfl_xor_sync(0xffffffffu, w, 1);
        w += __shfl_xor_sync(0xffffffffu, w, 2);

        float p = __expf(w);
        s += p;
        acc.x = fmaf(p, cur.x, acc.x);
        acc.y = fmaf(p, cur.y, acc.y);
        acc.z = fmaf(p, cur.z, acc.z);
        acc.w = fmaf(p, cur.w, acc.w);
    }

    const float inv = 1.0f / (s + 1e-16f);
    const float4 bi = *(const float4*)(bias + c);
    float4 o;
    o.x = acc.x * inv + bi.x;
    o.y = acc.y * inv + bi.y;
    o.z = acc.z * inv + bi.z;
    o.w = acc.w * inv + bi.w;
    *(float4*)(out + n * 128 + c) = o;
}

// ---------------- final head ----------------
__global__ void k_head(const float* __restrict__ xin, const float* __restrict__ w,
                       const float* __restrict__ bh, float* __restrict__ out)
{
    int gt   = blockIdx.x * blockDim.x + threadIdx.x;
    int warp = gt >> 5;
    int lane = gt & 31;
    if (warp >= (N_NODES / CHUNK) * NUM_LABELS) return;
    int c = warp / NUM_LABELS;
    int l = warp % NUM_LABELS;
    const float* row = xin + (c * CHUNK + l) * 128;
    float s = 0.0f;
    #pragma unroll
    for (int i = lane; i < 128; i += 32) s = fmaf(row[i], w[i], s);
    #pragma unroll
    for (int o = 16; o; o >>= 1) s += __shfl_down_sync(0xffffffffu, s, o);
    if (lane == 0) out[warp] = s + bh[0];
}

// ---------------- launch ----------------
extern "C" void kernel_launch(void* const* d_in, const int* in_sizes, int n_in,
                              void* d_out, int out_size)
{
    const float* x    = (const float*)d_in[0];
    const int*   eidx = (const int*)  d_in[1];
    // d_in[2] = nchunks (fixed = 8 -> CHUNK = 10)
    const float* Wl   = (const float*)d_in[3];
    const float* bl   = (const float*)d_in[4];
    const float* Wr   = (const float*)d_in[5];
    const float* br   = (const float*)d_in[6];
    const float* att  = (const float*)d_in[7];
    const float* bias = (const float*)d_in[8];
    const float* wh   = (const float*)d_in[9];
    const float* bh   = (const float*)d_in[10];
    float* out = (float*)d_out;

    float *bufA = nullptr, *bufB = nullptr;
    cudaGetSymbolAddress((void**)&bufA, g_bufA);
    cudaGetSymbolAddress((void**)&bufB, g_bufB);

    dim3 gg((N_NODES + 127) / 128, 2);
    const int layer_grid = (N_NODES + 7) / 8;

    // profiled slot #4 = k_gemm (layer 0)
    k_detect_zero<<<(N_NODES + 255) / 256, 256>>>(eidx);   // 1
    k_extract<<<(E_TOT + 255) / 256, 256>>>(eidx);         // 2
    k_scan<<<1, 1024>>>();                                 // 3
    k_gemm<<<gg, 256>>>(x, Wl, bl, Wr, br);                // 4  <-- profiled
    k_scatter<<<(E_TOT + 255) / 256, 256>>>();             // 5
    k_layer<<<layer_grid, 256>>>(att, bias, bufA);         // 6

    const float* cur = bufA;
    for (int l = 1; l < NUM_LAYERS; l++) {
        float* nxt = (l & 1) ? bufB : bufA;
        k_gemm<<<gg, 256>>>(cur,
                            Wl + l * D_MODEL * D_MODEL, bl + l * D_MODEL,
                            Wr + l * D_MODEL * D_MODEL, br + l * D_MODEL);
        k_layer<<<layer_grid, 256>>>(att + l * NHEAD * HEAD_DIM,
                                     bias + l * D_MODEL, nxt);
        cur = nxt;
    }
    int nwarp = (N_NODES / CHUNK) * NUM_LABELS;
    k_head<<<(nwarp * 32 + 255) / 256, 256>>>(cur, wh, bh, out);
}

// round 12
// speedup vs baseline: 1.5348x; 1.4270x over previous
#include <cuda_runtime.h>
#include <cuda_bf16.h>
#include <cstdint>

#define N_NODES   10000
#define N_EDGES   160000
#define E_TOT     170000
#define D_MODEL   128
#define NHEAD     8
#define HEAD_DIM  16
#define NUM_LAYERS 7
#define CHUNK     10
#define NUM_LABELS 2
#define NEG_SLOPE 0.2f

// GEMM geometry
#define TILE_M    64
#define GEMM_GX   ((N_NODES + TILE_M - 1) / TILE_M)   // 157
#define AROW      272                                  // bf16 row stride (bytes)
#define A_BYTES   (TILE_M * AROW)                      // 17408 (one of hi/lo)
#define B_BYTES   (128 * AROW)                         // 34816 (one of hi/lo)
#define GEMM_SMEM (2 * A_BYTES + 2 * B_BYTES)          // 104448

// ---------------- device scratch ----------------
__device__ float g_bufA[N_NODES * D_MODEL];
__device__ float g_bufB[N_NODES * D_MODEL];
__device__ float g_xl[N_NODES * D_MODEL];
__device__ float g_xr[N_NODES * D_MODEL];
__device__ int   g_src[E_TOT];
__device__ int   g_dst[E_TOT];
__device__ int   g_cnt[N_NODES];
__device__ int   g_start[N_NODES + 1];
__device__ int   g_cursor[N_NODES];
__device__ int   g_csr[E_TOT];
__device__ int   g_is64;
// W^T bf16 hi/lo: [layer][side][hi 32KB | lo 32KB], rows n (128), cols k (128)
__device__ __align__(16) unsigned char g_Bt[NUM_LAYERS * 2 * 65536];

// ---------------- helpers ----------------
__device__ __forceinline__ unsigned smem_u32(const void* p) {
    unsigned a;
    asm("{ .reg .u64 t; cvta.to.shared.u64 t, %1; cvt.u32.u64 %0, t; }"
        : "=r"(a) : "l"(p));
    return a;
}
__device__ __forceinline__ void cp16(unsigned s, const void* g) {
    asm volatile("cp.async.ca.shared.global [%0], [%1], 16;" :: "r"(s), "l"(g));
}
#define CP_COMMIT() asm volatile("cp.async.commit_group;")
#define CP_WAIT0()  asm volatile("cp.async.wait_group 0;" ::: "memory")

// split 8 consecutive floats into bf16 hi + bf16 lo(residual), packed uint4
__device__ __forceinline__ void bf16_split8(const float* f, uint4& hi, uint4& lo) {
    unsigned h[4], l[4];
    #pragma unroll
    for (int i = 0; i < 4; i++) {
        float a = f[2 * i], b = f[2 * i + 1];
        __nv_bfloat16 ha = __float2bfloat16(a);
        __nv_bfloat16 hb = __float2bfloat16(b);
        __nv_bfloat162 hp; hp.x = ha; hp.y = hb;
        h[i] = *reinterpret_cast<unsigned*>(&hp);
        __nv_bfloat162 lp;
        lp.x = __float2bfloat16(a - __bfloat162float(ha));
        lp.y = __float2bfloat16(b - __bfloat162float(hb));
        l[i] = *reinterpret_cast<unsigned*>(&lp);
    }
    hi = make_uint4(h[0], h[1], h[2], h[3]);
    lo = make_uint4(l[0], l[1], l[2], l[3]);
}

#define LDSM4(r0, r1, r2, r3, addr) \
    asm volatile("ldmatrix.sync.aligned.m8n8.x4.shared.b16 {%0,%1,%2,%3}, [%4];" \
                 : "=r"(r0), "=r"(r1), "=r"(r2), "=r"(r3) : "r"(addr))

#define MMA16816(d, a, b0, b1) \
    asm volatile("mma.sync.aligned.m16n8k16.row.col.f32.bf16.bf16.f32 " \
                 "{%0,%1,%2,%3}, {%4,%5,%6,%7}, {%8,%9}, {%0,%1,%2,%3};" \
                 : "+f"((d)[0]), "+f"((d)[1]), "+f"((d)[2]), "+f"((d)[3]) \
                 : "r"((a)[0]), "r"((a)[1]), "r"((a)[2]), "r"((a)[3]), \
                   "r"(b0), "r"(b1))

// ------------- dtype detect (int32 vs int64) + zero counters -------------
__global__ void k_detect_zero(const int* __restrict__ e32) {
    int t = blockIdx.x * blockDim.x + threadIdx.x;
    if (t < N_NODES) g_cnt[t] = 0;
    if (blockIdx.x == 0) {
        __shared__ int nz;
        if (threadIdx.x == 0) nz = 0;
        __syncthreads();
        for (int i = threadIdx.x; i < 1024; i += blockDim.x)
            if (e32[2 * i + 1] != 0) nz = 1;
        __syncthreads();
        if (threadIdx.x == 0) g_is64 = (nz == 0) ? 1 : 0;
    }
}

__global__ void k_extract(const int* __restrict__ e32) {
    int t = blockIdx.x * blockDim.x + threadIdx.x;
    if (t >= E_TOT) return;
    int s, d;
    if (t < N_EDGES) {
        if (g_is64) { s = e32[2 * t]; d = e32[2 * (N_EDGES + t)]; }
        else        { s = e32[t];     d = e32[N_EDGES + t]; }
    } else {
        s = t - N_EDGES; d = s;
    }
    g_src[t] = s;
    g_dst[t] = d;
    atomicAdd(&g_cnt[d], 1);
}

__global__ void __launch_bounds__(1024) k_scan() {
    __shared__ int warpsum[32];
    const int t    = threadIdx.x;
    const int lane = t & 31;
    const int warp = t >> 5;
    const int base = t * 10;

    int local[10];
    int sum = 0;
    #pragma unroll
    for (int i = 0; i < 10; i++) {
        int idx = base + i;
        local[i] = (idx < N_NODES) ? g_cnt[idx] : 0;
        sum += local[i];
    }
    int incl = sum;
    #pragma unroll
    for (int off = 1; off < 32; off <<= 1) {
        int v = __shfl_up_sync(0xffffffffu, incl, off);
        if (lane >= off) incl += v;
    }
    if (lane == 31) warpsum[warp] = incl;
    __syncthreads();
    if (warp == 0) {
        int w = warpsum[lane];
        int wi = w;
        #pragma unroll
        for (int off = 1; off < 32; off <<= 1) {
            int v = __shfl_up_sync(0xffffffffu, wi, off);
            if (lane >= off) wi += v;
        }
        warpsum[lane] = wi - w;
    }
    __syncthreads();
    int run = warpsum[warp] + (incl - sum);
    #pragma unroll
    for (int i = 0; i < 10; i++) {
        int idx = base + i;
        if (idx < N_NODES) {
            g_start[idx]  = run;
            g_cursor[idx] = run;
        }
        run += local[i];
    }
    if (t == 0) g_start[N_NODES] = E_TOT;
}

__global__ void k_scatter() {
    int t = blockIdx.x * blockDim.x + threadIdx.x;
    if (t >= E_TOT) return;
    int d = g_dst[t];
    int pos = atomicAdd(&g_cursor[d], 1);
    g_csr[pos] = g_src[t];
}

// ---------------- W prep: W[k][n] fp32 -> Wt[n][k] bf16 hi/lo -------------
// grid = NUM_LAYERS*2 (l*2+side), 256 threads
__global__ void __launch_bounds__(256) k_prep(
    const float* __restrict__ Wl, const float* __restrict__ Wr)
{
    __shared__ float sw[32][129];
    const int l    = blockIdx.x >> 1;
    const int side = blockIdx.x & 1;
    const float* W = (side ? Wr : Wl) + l * D_MODEL * D_MODEL;
    unsigned char* gH = g_Bt + (size_t)blockIdx.x * 65536;
    unsigned char* gL = gH + 32768;
    const int tid = threadIdx.x;

    for (int k0 = 0; k0 < 128; k0 += 32) {
        for (int i = tid; i < 32 * 128; i += 256) {
            int k = i >> 7, n = i & 127;
            sw[k][n] = W[(k0 + k) * 128 + n];
        }
        __syncthreads();
        const int n  = tid >> 1;
        const int kh = (tid & 1) * 16;
        #pragma unroll
        for (int half = 0; half < 2; half++) {
            int kk = kh + half * 8;
            float f[8];
            #pragma unroll
            for (int j = 0; j < 8; j++) f[j] = sw[kk + j][n];
            uint4 hi, lo;
            bf16_split8(f, hi, lo);
            *(uint4*)(gH + n * 256 + (k0 + kk) * 2) = hi;
            *(uint4*)(gL + n * 256 + (k0 + kk) * 2) = lo;
        }
        __syncthreads();
    }
}

// ---------------- tensor-core GEMM: out = X @ W + b (per side) -----------
// 64x128 block tile, 8 warps (2m x 4n -> warp tile m32 x n32), K=128.
// bf16 3-pass split: Ahi*Bhi + Alo*Bhi + Ahi*Blo, fp32 accum.
__global__ void __launch_bounds__(256) k_gemm(
    const float* __restrict__ X, const unsigned char* __restrict__ gB_layer,
    const float* __restrict__ bl, const float* __restrict__ br)
{
    extern __shared__ char dsm[];
    char* Ahi = dsm;
    char* Alo = dsm + A_BYTES;
    char* Bhi = dsm + 2 * A_BYTES;
    char* Blo = dsm + 2 * A_BYTES + B_BYTES;

    const int tid  = threadIdx.x;
    const int warp = tid >> 5;
    const int lane = tid & 31;
    const int side = blockIdx.y;
    const int row0 = blockIdx.x * TILE_M;

    const unsigned char* gB = gB_layer + side * 65536;
    const float* bias = side ? br : bl;
    float* out = side ? g_xr : g_xl;

    // B copy: hi+lo, 128 rows x 16 chunks each = 4096 chunks, 16/thread
    {
        const unsigned bh = smem_u32(Bhi);
        const unsigned blo = smem_u32(Blo);
        #pragma unroll
        for (int i = 0; i < 16; i++) {
            int c   = tid + i * 256;
            int sel = c >> 11;
            int cc  = c & 2047;
            int r   = cc >> 4;
            int ch  = cc & 15;
            unsigned dst = (sel ? blo : bh) + r * AROW + ch * 16;
            cp16(dst, gB + sel * 32768 + r * 256 + ch * 16);
        }
        CP_COMMIT();
    }

    // A convert: 64 rows x 16 chunks(8 el) = 1024 chunks, 4/thread
    #pragma unroll
    for (int i = 0; i < 4; i++) {
        int c  = tid + i * 256;
        int r  = c >> 4;
        int k0 = (c & 15) * 8;
        int gr = row0 + r;
        if (gr >= N_NODES) gr = N_NODES - 1;     // clamp; rows unstored later
        float f[8];
        *(float4*)(f)     = *(const float4*)(X + gr * 128 + k0);
        *(float4*)(f + 4) = *(const float4*)(X + gr * 128 + k0 + 4);
        uint4 hi, lo;
        bf16_split8(f, hi, lo);
        *(uint4*)(Ahi + r * AROW + k0 * 2) = hi;
        *(uint4*)(Alo + r * AROW + k0 * 2) = lo;
    }
    CP_WAIT0();
    __syncthreads();

    const int wm = warp >> 2;     // 0..1 -> m offset wm*32
    const int wn = warp & 3;      // 0..3 -> n offset wn*32

    float acc[2][4][4];
    #pragma unroll
    for (int mt = 0; mt < 2; mt++)
        #pragma unroll
        for (int nt = 0; nt < 4; nt++)
            #pragma unroll
            for (int q = 0; q < 4; q++) acc[mt][nt][q] = 0.0f;

    const unsigned laneOff = (lane & 15) * AROW + (lane >> 4) * 16;
    const unsigned aHiBase = smem_u32(Ahi) + wm * 32 * AROW + laneOff;
    const unsigned aLoBase = smem_u32(Alo) + wm * 32 * AROW + laneOff;
    const unsigned bHiBase = smem_u32(Bhi) + wn * 32 * AROW + laneOff;
    const unsigned bLoBase = smem_u32(Blo) + wn * 32 * AROW + laneOff;

    #pragma unroll
    for (int pass = 0; pass < 3; pass++) {
        const unsigned aBase = (pass == 1) ? aLoBase : aHiBase;
        const unsigned bBase = (pass == 2) ? bLoBase : bHiBase;
        #pragma unroll
        for (int kc = 0; kc < 8; kc++) {
            const unsigned kb = kc * 32;             // 16 halfs = 32 bytes
            unsigned A0[4], A1[4], B0[4], B1[4];
            LDSM4(A0[0], A0[1], A0[2], A0[3], aBase + kb);
            LDSM4(A1[0], A1[1], A1[2], A1[3], aBase + kb + 16 * AROW);
            LDSM4(B0[0], B0[1], B0[2], B0[3], bBase + kb);
            LDSM4(B1[0], B1[1], B1[2], B1[3], bBase + kb + 16 * AROW);
            MMA16816(acc[0][0], A0, B0[0], B0[2]);
            MMA16816(acc[0][1], A0, B0[1], B0[3]);
            MMA16816(acc[0][2], A0, B1[0], B1[2]);
            MMA16816(acc[0][3], A0, B1[1], B1[3]);
            MMA16816(acc[1][0], A1, B0[0], B0[2]);
            MMA16816(acc[1][1], A1, B0[1], B0[3]);
            MMA16816(acc[1][2], A1, B1[0], B1[2]);
            MMA16816(acc[1][3], A1, B1[1], B1[3]);
        }
    }

    // epilogue: c-fragment rows (lane>>2, +8), cols (lane&3)*2, +1
    #pragma unroll
    for (int mt = 0; mt < 2; mt++) {
        const int rbase = row0 + wm * 32 + mt * 16 + (lane >> 2);
        #pragma unroll
        for (int nt = 0; nt < 4; nt++) {
            const int col = wn * 32 + nt * 8 + (lane & 3) * 2;
            const float b0 = bias[col], b1 = bias[col + 1];
            if (rbase < N_NODES) {
                float2 o; o.x = acc[mt][nt][0] + b0; o.y = acc[mt][nt][1] + b1;
                *(float2*)(out + rbase * 128 + col) = o;
            }
            if (rbase + 8 < N_NODES) {
                float2 o; o.x = acc[mt][nt][2] + b0; o.y = acc[mt][nt][3] + b1;
                *(float2*)(out + (rbase + 8) * 128 + col) = o;
            }
        }
    }
}

// ---------------- fused edge kernel: NO-MAX softmax + aggregate ----------
__global__ void __launch_bounds__(256) k_layer(
    const float* __restrict__ att, const float* __restrict__ bias,
    float* __restrict__ out)
{
    const int warp = threadIdx.x >> 5;
    const int n    = blockIdx.x * 8 + warp;
    if (n >= N_NODES) return;
    const int lane = threadIdx.x & 31;
    const int c    = lane * 4;

    const float4 xr = *(const float4*)(g_xr + n * 128 + c);
    const float4 av = *(const float4*)(att + c);

    const int beg = g_start[n];
    const int end = g_start[n + 1];

    float  s = 0.0f;
    float4 acc = make_float4(0.f, 0.f, 0.f, 0.f);

    float4 v0 = *(const float4*)(g_xl + g_csr[beg] * 128 + c);
    float4 v1 = (beg + 1 < end)
        ? *(const float4*)(g_xl + g_csr[beg + 1] * 128 + c) : v0;

    for (int e = beg; e < end; e++) {
        float4 cur = v0;
        v0 = v1;
        if (e + 2 < end)
            v1 = *(const float4*)(g_xl + g_csr[e + 2] * 128 + c);

        float zx = cur.x + xr.x; zx = fmaxf(zx, NEG_SLOPE * zx);
        float zy = cur.y + xr.y; zy = fmaxf(zy, NEG_SLOPE * zy);
        float zz = cur.z + xr.z; zz = fmaxf(zz, NEG_SLOPE * zz);
        float zw = cur.w + xr.w; zw = fmaxf(zw, NEG_SLOPE * zw);
        float w = zx * av.x;
        w = fmaf(zy, av.y, w);
        w = fmaf(zz, av.z, w);
        w = fmaf(zw, av.w, w);
        w += __shfl_xor_sync(0xffffffffu, w, 1);
        w += __shfl_xor_sync(0xffffffffu, w, 2);

        float p = __expf(w);
        s += p;
        acc.x = fmaf(p, cur.x, acc.x);
        acc.y = fmaf(p, cur.y, acc.y);
        acc.z = fmaf(p, cur.z, acc.z);
        acc.w = fmaf(p, cur.w, acc.w);
    }

    const float inv = 1.0f / (s + 1e-16f);
    const float4 bi = *(const float4*)(bias + c);
    float4 o;
    o.x = acc.x * inv + bi.x;
    o.y = acc.y * inv + bi.y;
    o.z = acc.z * inv + bi.z;
    o.w = acc.w * inv + bi.w;
    *(float4*)(out + n * 128 + c) = o;
}

// ---------------- final head ----------------
__global__ void k_head(const float* __restrict__ xin, const float* __restrict__ w,
                       const float* __restrict__ bh, float* __restrict__ out)
{
    int gt   = blockIdx.x * blockDim.x + threadIdx.x;
    int warp = gt >> 5;
    int lane = gt & 31;
    if (warp >= (N_NODES / CHUNK) * NUM_LABELS) return;
    int c = warp / NUM_LABELS;
    int l = warp % NUM_LABELS;
    const float* row = xin + (c * CHUNK + l) * 128;
    float s = 0.0f;
    #pragma unroll
    for (int i = lane; i < 128; i += 32) s = fmaf(row[i], w[i], s);
    #pragma unroll
    for (int o = 16; o; o >>= 1) s += __shfl_down_sync(0xffffffffu, s, o);
    if (lane == 0) out[warp] = s + bh[0];
}

// ---------------- launch ----------------
extern "C" void kernel_launch(void* const* d_in, const int* in_sizes, int n_in,
                              void* d_out, int out_size)
{
    const float* x    = (const float*)d_in[0];
    const int*   eidx = (const int*)  d_in[1];
    // d_in[2] = nchunks (fixed = 8 -> CHUNK = 10)
    const float* Wl   = (const float*)d_in[3];
    const float* bl   = (const float*)d_in[4];
    const float* Wr   = (const float*)d_in[5];
    const float* br   = (const float*)d_in[6];
    const float* att  = (const float*)d_in[7];
    const float* bias = (const float*)d_in[8];
    const float* wh   = (const float*)d_in[9];
    const float* bh   = (const float*)d_in[10];
    float* out = (float*)d_out;

    cudaFuncSetAttribute(k_gemm, cudaFuncAttributeMaxDynamicSharedMemorySize,
                         GEMM_SMEM);

    float *bufA = nullptr, *bufB = nullptr;
    cudaGetSymbolAddress((void**)&bufA, g_bufA);
    cudaGetSymbolAddress((void**)&bufB, g_bufB);
    unsigned char* gBt = nullptr;
    cudaGetSymbolAddress((void**)&gBt, g_Bt);

    dim3 gg(GEMM_GX, 2);
    const int layer_grid = (N_NODES + 7) / 8;

    // profiled slot #4 = k_gemm (layer 0)
    k_detect_zero<<<(N_NODES + 255) / 256, 256>>>(eidx);       // 1
    k_extract<<<(E_TOT + 255) / 256, 256>>>(eidx);             // 2
    k_prep<<<NUM_LAYERS * 2, 256>>>(Wl, Wr);                   // 3
    k_gemm<<<gg, 256, GEMM_SMEM>>>(x, gBt, bl, br);            // 4 <-- profiled
    k_scan<<<1, 1024>>>();                                     // 5
    k_scatter<<<(E_TOT + 255) / 256, 256>>>();                 // 6
    k_layer<<<layer_grid, 256>>>(att, bias, bufA);             // 7

    const float* cur = bufA;
    for (int l = 1; l < NUM_LAYERS; l++) {
        float* nxt = (l & 1) ? bufB : bufA;
        k_gemm<<<gg, 256, GEMM_SMEM>>>(cur, gBt + (size_t)l * 131072,
                                       bl + l * D_MODEL, br + l * D_MODEL);
        k_layer<<<layer_grid, 256>>>(att + l * NHEAD * HEAD_DIM,
                                     bias + l * D_MODEL, nxt);
        cur = nxt;
    }
    int nwarp = (N_NODES / CHUNK) * NUM_LABELS;
    k_head<<<(nwarp * 32 + 255) / 256, 256>>>(cur, wh, bh, out);
}

// round 13
// speedup vs baseline: 1.5480x; 1.0086x over previous
#include <cuda_runtime.h>
#include <cuda_bf16.h>
#include <cstdint>

#define N_NODES   10000
#define N_EDGES   160000
#define E_TOT     170000
#define D_MODEL   128
#define NHEAD     8
#define HEAD_DIM  16
#define NUM_LAYERS 7
#define CHUNK     10
#define NUM_LABELS 2
#define NEG_SLOPE 0.2f

// GEMM geometry
#define TILE_M    64
#define GEMM_GX   ((N_NODES + TILE_M - 1) / TILE_M)   // 157
#define AROW      272                                  // bf16 row stride (bytes)
#define A_BYTES   (TILE_M * AROW)                      // 17408 (one of hi/lo)
#define B_BYTES   (128 * AROW)                         // 34816 (one of hi/lo)
#define GEMM_SMEM (2 * A_BYTES + 2 * B_BYTES)          // 104448

// ---------------- device scratch ----------------
__device__ float g_bufA[N_NODES * D_MODEL];
__device__ float g_bufB[N_NODES * D_MODEL];
__device__ float g_xl[N_NODES * D_MODEL];
__device__ float g_xr[N_NODES * D_MODEL];
__device__ int   g_src[E_TOT];
__device__ int   g_dst[E_TOT];
__device__ int   g_cnt[N_NODES];          // zero-init; k_scan re-zeros each run
__device__ int   g_start[N_NODES + 1];
__device__ int   g_cursor[N_NODES];
__device__ int   g_csr[E_TOT];
__device__ int   g_is64;
// W^T bf16 hi/lo: [layer][side][hi 32KB | lo 32KB], rows n (128), cols k (128)
__device__ __align__(16) unsigned char g_Bt[NUM_LAYERS * 2 * 65536];

// ---------------- helpers ----------------
__device__ __forceinline__ unsigned smem_u32(const void* p) {
    unsigned a;
    asm("{ .reg .u64 t; cvta.to.shared.u64 t, %1; cvt.u32.u64 %0, t; }"
        : "=r"(a) : "l"(p));
    return a;
}
__device__ __forceinline__ void cp16(unsigned s, const void* g) {
    asm volatile("cp.async.ca.shared.global [%0], [%1], 16;" :: "r"(s), "l"(g));
}
#define CP_COMMIT() asm volatile("cp.async.commit_group;")
#define CP_WAIT0()  asm volatile("cp.async.wait_group 0;" ::: "memory")

// split 8 consecutive floats into bf16 hi + bf16 lo(residual), packed uint4
__device__ __forceinline__ void bf16_split8(const float* f, uint4& hi, uint4& lo) {
    unsigned h[4], l[4];
    #pragma unroll
    for (int i = 0; i < 4; i++) {
        float a = f[2 * i], b = f[2 * i + 1];
        __nv_bfloat16 ha = __float2bfloat16(a);
        __nv_bfloat16 hb = __float2bfloat16(b);
        __nv_bfloat162 hp; hp.x = ha; hp.y = hb;
        h[i] = *reinterpret_cast<unsigned*>(&hp);
        __nv_bfloat162 lp;
        lp.x = __float2bfloat16(a - __bfloat162float(ha));
        lp.y = __float2bfloat16(b - __bfloat162float(hb));
        l[i] = *reinterpret_cast<unsigned*>(&lp);
    }
    hi = make_uint4(h[0], h[1], h[2], h[3]);
    lo = make_uint4(l[0], l[1], l[2], l[3]);
}

#define LDSM4(r0, r1, r2, r3, addr) \
    asm volatile("ldmatrix.sync.aligned.m8n8.x4.shared.b16 {%0,%1,%2,%3}, [%4];" \
                 : "=r"(r0), "=r"(r1), "=r"(r2), "=r"(r3) : "r"(addr))

#define MMA16816(d, a, b0, b1) \
    asm volatile("mma.sync.aligned.m16n8k16.row.col.f32.bf16.bf16.f32 " \
                 "{%0,%1,%2,%3}, {%4,%5,%6,%7}, {%8,%9}, {%0,%1,%2,%3};" \
                 : "+f"((d)[0]), "+f"((d)[1]), "+f"((d)[2]), "+f"((d)[3]) \
                 : "r"((a)[0]), "r"((a)[1]), "r"((a)[2]), "r"((a)[3]), \
                   "r"(b0), "r"(b1))

// ------------- dtype detect (int32 vs int64), 1 block -------------
__global__ void k_detect(const int* __restrict__ e32) {
    __shared__ int nz;
    if (threadIdx.x == 0) nz = 0;
    __syncthreads();
    for (int i = threadIdx.x; i < 1024; i += blockDim.x)
        if (e32[2 * i + 1] != 0) nz = 1;
    __syncthreads();
    if (threadIdx.x == 0) g_is64 = (nz == 0) ? 1 : 0;
}

__global__ void k_extract(const int* __restrict__ e32) {
    int t = blockIdx.x * blockDim.x + threadIdx.x;
    if (t >= E_TOT) return;
    int s, d;
    if (t < N_EDGES) {
        if (g_is64) { s = e32[2 * t]; d = e32[2 * (N_EDGES + t)]; }
        else        { s = e32[t];     d = e32[N_EDGES + t]; }
    } else {
        s = t - N_EDGES; d = s;
    }
    g_src[t] = s;
    g_dst[t] = d;
    atomicAdd(&g_cnt[d], 1);
}

// exclusive scan of g_cnt -> g_start/g_cursor; RE-ZEROS g_cnt for the next
// graph replay (counters invariant: zero at entry of every kernel_launch).
__global__ void __launch_bounds__(1024) k_scan() {
    __shared__ int warpsum[32];
    const int t    = threadIdx.x;
    const int lane = t & 31;
    const int warp = t >> 5;
    const int base = t * 10;

    int local[10];
    int sum = 0;
    #pragma unroll
    for (int i = 0; i < 10; i++) {
        int idx = base + i;
        local[i] = (idx < N_NODES) ? g_cnt[idx] : 0;
        if (idx < N_NODES) g_cnt[idx] = 0;
        sum += local[i];
    }
    int incl = sum;
    #pragma unroll
    for (int off = 1; off < 32; off <<= 1) {
        int v = __shfl_up_sync(0xffffffffu, incl, off);
        if (lane >= off) incl += v;
    }
    if (lane == 31) warpsum[warp] = incl;
    __syncthreads();
    if (warp == 0) {
        int w = warpsum[lane];
        int wi = w;
        #pragma unroll
        for (int off = 1; off < 32; off <<= 1) {
            int v = __shfl_up_sync(0xffffffffu, wi, off);
            if (lane >= off) wi += v;
        }
        warpsum[lane] = wi - w;
    }
    __syncthreads();
    int run = warpsum[warp] + (incl - sum);
    #pragma unroll
    for (int i = 0; i < 10; i++) {
        int idx = base + i;
        if (idx < N_NODES) {
            g_start[idx]  = run;
            g_cursor[idx] = run;
        }
        run += local[i];
    }
    if (t == 0) g_start[N_NODES] = E_TOT;
}

__global__ void k_scatter() {
    int t = blockIdx.x * blockDim.x + threadIdx.x;
    if (t >= E_TOT) return;
    int d = g_dst[t];
    int pos = atomicAdd(&g_cursor[d], 1);
    g_csr[pos] = g_src[t];
}

// ---------------- W prep: W[k][n] fp32 -> Wt[n][k] bf16 hi/lo -------------
__global__ void __launch_bounds__(256) k_prep(
    const float* __restrict__ Wl, const float* __restrict__ Wr)
{
    __shared__ float sw[32][129];
    const int l    = blockIdx.x >> 1;
    const int side = blockIdx.x & 1;
    const float* W = (side ? Wr : Wl) + l * D_MODEL * D_MODEL;
    unsigned char* gH = g_Bt + (size_t)blockIdx.x * 65536;
    unsigned char* gL = gH + 32768;
    const int tid = threadIdx.x;

    for (int k0 = 0; k0 < 128; k0 += 32) {
        for (int i = tid; i < 32 * 128; i += 256) {
            int k = i >> 7, n = i & 127;
            sw[k][n] = W[(k0 + k) * 128 + n];
        }
        __syncthreads();
        const int n  = tid >> 1;
        const int kh = (tid & 1) * 16;
        #pragma unroll
        for (int half = 0; half < 2; half++) {
            int kk = kh + half * 8;
            float f[8];
            #pragma unroll
            for (int j = 0; j < 8; j++) f[j] = sw[kk + j][n];
            uint4 hi, lo;
            bf16_split8(f, hi, lo);
            *(uint4*)(gH + n * 256 + (k0 + kk) * 2) = hi;
            *(uint4*)(gL + n * 256 + (k0 + kk) * 2) = lo;
        }
        __syncthreads();
    }
}

// ---------------- tensor-core GEMM: out = X @ W + b (per side) -----------
// 64x128 block tile, 8 warps (2m x 4n -> warp tile m32 x n32), K=128.
// bf16 3-pass split: Ahi*Bhi + Alo*Bhi + Ahi*Blo, fp32 accum.
// launch_bounds(256,2): 2 blocks/SM (regs<=128, smem 2x104KB fits 228KB).
__global__ void __launch_bounds__(256, 2) k_gemm(
    const float* __restrict__ X, const unsigned char* __restrict__ gB_layer,
    const float* __restrict__ bl, const float* __restrict__ br)
{
    extern __shared__ char dsm[];
    char* Ahi = dsm;
    char* Alo = dsm + A_BYTES;
    char* Bhi = dsm + 2 * A_BYTES;
    char* Blo = dsm + 2 * A_BYTES + B_BYTES;

    const int tid  = threadIdx.x;
    const int warp = tid >> 5;
    const int lane = tid & 31;
    const int side = blockIdx.y;
    const int row0 = blockIdx.x * TILE_M;

    const unsigned char* gB = gB_layer + side * 65536;
    const float* bias = side ? br : bl;
    float* out = side ? g_xr : g_xl;

    // B copy: hi+lo, 128 rows x 16 chunks each = 4096 chunks, 16/thread
    {
        const unsigned bh = smem_u32(Bhi);
        const unsigned blo = smem_u32(Blo);
        #pragma unroll
        for (int i = 0; i < 16; i++) {
            int c   = tid + i * 256;
            int sel = c >> 11;
            int cc  = c & 2047;
            int r   = cc >> 4;
            int ch  = cc & 15;
            unsigned dst = (sel ? blo : bh) + r * AROW + ch * 16;
            cp16(dst, gB + sel * 32768 + r * 256 + ch * 16);
        }
        CP_COMMIT();
    }

    // A convert: 64 rows x 16 chunks(8 el) = 1024 chunks, 4/thread
    #pragma unroll
    for (int i = 0; i < 4; i++) {
        int c  = tid + i * 256;
        int r  = c >> 4;
        int k0 = (c & 15) * 8;
        int gr = row0 + r;
        if (gr >= N_NODES) gr = N_NODES - 1;     // clamp; rows unstored later
        float f[8];
        *(float4*)(f)     = *(const float4*)(X + gr * 128 + k0);
        *(float4*)(f + 4) = *(const float4*)(X + gr * 128 + k0 + 4);
        uint4 hi, lo;
        bf16_split8(f, hi, lo);
        *(uint4*)(Ahi + r * AROW + k0 * 2) = hi;
        *(uint4*)(Alo + r * AROW + k0 * 2) = lo;
    }
    CP_WAIT0();
    __syncthreads();

    const int wm = warp >> 2;     // 0..1 -> m offset wm*32
    const int wn = warp & 3;      // 0..3 -> n offset wn*32

    float acc[2][4][4];
    #pragma unroll
    for (int mt = 0; mt < 2; mt++)
        #pragma unroll
        for (int nt = 0; nt < 4; nt++)
            #pragma unroll
            for (int q = 0; q < 4; q++) acc[mt][nt][q] = 0.0f;

    const unsigned laneOff = (lane & 15) * AROW + (lane >> 4) * 16;
    const unsigned aHiBase = smem_u32(Ahi) + wm * 32 * AROW + laneOff;
    const unsigned aLoBase = smem_u32(Alo) + wm * 32 * AROW + laneOff;
    const unsigned bHiBase = smem_u32(Bhi) + wn * 32 * AROW + laneOff;
    const unsigned bLoBase = smem_u32(Blo) + wn * 32 * AROW + laneOff;

    #pragma unroll 1
    for (int pass = 0; pass < 3; pass++) {
        const unsigned aBase = (pass == 1) ? aLoBase : aHiBase;
        const unsigned bBase = (pass == 2) ? bLoBase : bHiBase;
        #pragma unroll
        for (int kc = 0; kc < 8; kc++) {
            const unsigned kb = kc * 32;             // 16 halfs = 32 bytes
            unsigned A0[4], A1[4], B0[4], B1[4];
            LDSM4(A0[0], A0[1], A0[2], A0[3], aBase + kb);
            LDSM4(A1[0], A1[1], A1[2], A1[3], aBase + kb + 16 * AROW);
            LDSM4(B0[0], B0[1], B0[2], B0[3], bBase + kb);
            LDSM4(B1[0], B1[1], B1[2], B1[3], bBase + kb + 16 * AROW);
            MMA16816(acc[0][0], A0, B0[0], B0[2]);
            MMA16816(acc[0][1], A0, B0[1], B0[3]);
            MMA16816(acc[0][2], A0, B1[0], B1[2]);
            MMA16816(acc[0][3], A0, B1[1], B1[3]);
            MMA16816(acc[1][0], A1, B0[0], B0[2]);
            MMA16816(acc[1][1], A1, B0[1], B0[3]);
            MMA16816(acc[1][2], A1, B1[0], B1[2]);
            MMA16816(acc[1][3], A1, B1[1], B1[3]);
        }
    }

    // epilogue: c-fragment rows (lane>>2, +8), cols (lane&3)*2, +1
    #pragma unroll
    for (int mt = 0; mt < 2; mt++) {
        const int rbase = row0 + wm * 32 + mt * 16 + (lane >> 2);
        #pragma unroll
        for (int nt = 0; nt < 4; nt++) {
            const int col = wn * 32 + nt * 8 + (lane & 3) * 2;
            const float b0 = bias[col], b1 = bias[col + 1];
            if (rbase < N_NODES) {
                float2 o; o.x = acc[mt][nt][0] + b0; o.y = acc[mt][nt][1] + b1;
                *(float2*)(out + rbase * 128 + col) = o;
            }
            if (rbase + 8 < N_NODES) {
                float2 o; o.x = acc[mt][nt][2] + b0; o.y = acc[mt][nt][3] + b1;
                *(float2*)(out + (rbase + 8) * 128 + col) = o;
            }
        }
    }
}

// ---------------- fused edge kernel: NO-MAX softmax + aggregate ----------
__global__ void __launch_bounds__(256) k_layer(
    const float* __restrict__ att, const float* __restrict__ bias,
    float* __restrict__ out)
{
    const int warp = threadIdx.x >> 5;
    const int n    = blockIdx.x * 8 + warp;
    if (n >= N_NODES) return;
    const int lane = threadIdx.x & 31;
    const int c    = lane * 4;

    const float4 xr = *(const float4*)(g_xr + n * 128 + c);
    const float4 av = *(const float4*)(att + c);

    const int beg = g_start[n];
    const int end = g_start[n + 1];

    float  s = 0.0f;
    float4 acc = make_float4(0.f, 0.f, 0.f, 0.f);

    float4 v0 = *(const float4*)(g_xl + g_csr[beg] * 128 + c);
    float4 v1 = (beg + 1 < end)
        ? *(const float4*)(g_xl + g_csr[beg + 1] * 128 + c) : v0;

    for (int e = beg; e < end; e++) {
        float4 cur = v0;
        v0 = v1;
        if (e + 2 < end)
            v1 = *(const float4*)(g_xl + g_csr[e + 2] * 128 + c);

        float zx = cur.x + xr.x; zx = fmaxf(zx, NEG_SLOPE * zx);
        float zy = cur.y + xr.y; zy = fmaxf(zy, NEG_SLOPE * zy);
        float zz = cur.z + xr.z; zz = fmaxf(zz, NEG_SLOPE * zz);
        float zw = cur.w + xr.w; zw = fmaxf(zw, NEG_SLOPE * zw);
        float w = zx * av.x;
        w = fmaf(zy, av.y, w);
        w = fmaf(zz, av.z, w);
        w = fmaf(zw, av.w, w);
        w += __shfl_xor_sync(0xffffffffu, w, 1);
        w += __shfl_xor_sync(0xffffffffu, w, 2);

        float p = __expf(w);
        s += p;
        acc.x = fmaf(p, cur.x, acc.x);
        acc.y = fmaf(p, cur.y, acc.y);
        acc.z = fmaf(p, cur.z, acc.z);
        acc.w = fmaf(p, cur.w, acc.w);
    }

    const float inv = 1.0f / (s + 1e-16f);
    const float4 bi = *(const float4*)(bias + c);
    float4 o;
    o.x = acc.x * inv + bi.x;
    o.y = acc.y * inv + bi.y;
    o.z = acc.z * inv + bi.z;
    o.w = acc.w * inv + bi.w;
    *(float4*)(out + n * 128 + c) = o;
}

// ---------------- final head ----------------
__global__ void k_head(const float* __restrict__ xin, const float* __restrict__ w,
                       const float* __restrict__ bh, float* __restrict__ out)
{
    int gt   = blockIdx.x * blockDim.x + threadIdx.x;
    int warp = gt >> 5;
    int lane = gt & 31;
    if (warp >= (N_NODES / CHUNK) * NUM_LABELS) return;
    int c = warp / NUM_LABELS;
    int l = warp % NUM_LABELS;
    const float* row = xin + (c * CHUNK + l) * 128;
    float s = 0.0f;
    #pragma unroll
    for (int i = lane; i < 128; i += 32) s = fmaf(row[i], w[i], s);
    #pragma unroll
    for (int o = 16; o; o >>= 1) s += __shfl_down_sync(0xffffffffu, s, o);
    if (lane == 0) out[warp] = s + bh[0];
}

// ---------------- launch ----------------
extern "C" void kernel_launch(void* const* d_in, const int* in_sizes, int n_in,
                              void* d_out, int out_size)
{
    const float* x    = (const float*)d_in[0];
    const int*   eidx = (const int*)  d_in[1];
    // d_in[2] = nchunks (fixed = 8 -> CHUNK = 10)
    const float* Wl   = (const float*)d_in[3];
    const float* bl   = (const float*)d_in[4];
    const float* Wr   = (const float*)d_in[5];
    const float* br   = (const float*)d_in[6];
    const float* att  = (const float*)d_in[7];
    const float* bias = (const float*)d_in[8];
    const float* wh   = (const float*)d_in[9];
    const float* bh   = (const float*)d_in[10];
    float* out = (float*)d_out;

    cudaFuncSetAttribute(k_gemm, cudaFuncAttributeMaxDynamicSharedMemorySize,
                         GEMM_SMEM);

    float *bufA = nullptr, *bufB = nullptr;
    cudaGetSymbolAddress((void**)&bufA, g_bufA);
    cudaGetSymbolAddress((void**)&bufB, g_bufB);
    unsigned char* gBt = nullptr;
    cudaGetSymbolAddress((void**)&gBt, g_Bt);

    dim3 gg(GEMM_GX, 2);
    const int layer_grid = (N_NODES + 7) / 8;

    // profiled slot #4 = k_gemm (layer 0)
    k_detect<<<1, 256>>>(eidx);                                // 1
    k_extract<<<(E_TOT + 255) / 256, 256>>>(eidx);             // 2
    k_prep<<<NUM_LAYERS * 2, 256>>>(Wl, Wr);                   // 3
    k_gemm<<<gg, 256, GEMM_SMEM>>>(x, gBt, bl, br);            // 4 <-- profiled
    k_scan<<<1, 1024>>>();                                     // 5
    k_scatter<<<(E_TOT + 255) / 256, 256>>>();                 // 6
    k_layer<<<layer_grid, 256>>>(att, bias, bufA);             // 7

    const float* cur = bufA;
    for (int l = 1; l < NUM_LAYERS; l++) {
        float* nxt = (l & 1) ? bufB : bufA;
        k_gemm<<<gg, 256, GEMM_SMEM>>>(cur, gBt + (size_t)l * 131072,
                                       bl + l * D_MODEL, br + l * D_MODEL);
        k_layer<<<layer_grid, 256>>>(att + l * NHEAD * HEAD_DIM,
                                     bias + l * D_MODEL, nxt);
        cur = nxt;
    }
    int nwarp = (N_NODES / CHUNK) * NUM_LABELS;
    k_head<<<(nwarp * 32 + 255) / 256, 256>>>(cur, wh, bh, out);
}

// round 14
// speedup vs baseline: 1.5492x; 1.0008x over previous
#include <cuda_runtime.h>
#include <cuda_bf16.h>
#include <cstdint>

#define N_NODES   10000
#define N_EDGES   160000
#define E_TOT     170000
#define D_MODEL   128
#define NHEAD     8
#define HEAD_DIM  16
#define NUM_LAYERS 7
#define CHUNK     10
#define NUM_LABELS 2
#define NEG_SLOPE 0.2f

// GEMM geometry
#define TILE_M    64
#define GEMM_GX   ((N_NODES + TILE_M - 1) / TILE_M)   // 157
#define AROW      272                                  // bf16 row stride (bytes)
#define A_BYTES   (TILE_M * AROW)                      // 17408 (one of hi/lo)
#define B_BYTES   (128 * AROW)                         // 34816 (one of hi/lo)
#define GEMM_SMEM (2 * A_BYTES + 2 * B_BYTES)          // 104448

// ---------------- device scratch ----------------
__device__ float g_xl[N_NODES * D_MODEL];
__device__ float g_xr[N_NODES * D_MODEL];
// activations in bf16 hi/lo planes (current layer input)
__device__ __align__(16) unsigned short g_Ahi[N_NODES * D_MODEL];
__device__ __align__(16) unsigned short g_Alo[N_NODES * D_MODEL];
__device__ int   g_src[E_TOT];
__device__ int   g_dst[E_TOT];
__device__ int   g_cnt[N_NODES];          // zero-init; k_scan re-zeros each run
__device__ int   g_start[N_NODES + 1];
__device__ int   g_cursor[N_NODES];
__device__ int   g_csr[E_TOT];
__device__ int   g_is64;
// W^T bf16 hi/lo: [layer][side][hi 32KB | lo 32KB], rows n (128), cols k (128)
__device__ __align__(16) unsigned char g_Bt[NUM_LAYERS * 2 * 65536];

// ---------------- helpers ----------------
__device__ __forceinline__ unsigned smem_u32(const void* p) {
    unsigned a;
    asm("{ .reg .u64 t; cvta.to.shared.u64 t, %1; cvt.u32.u64 %0, t; }"
        : "=r"(a) : "l"(p));
    return a;
}
__device__ __forceinline__ void cp16(unsigned s, const void* g) {
    asm volatile("cp.async.ca.shared.global [%0], [%1], 16;" :: "r"(s), "l"(g));
}
#define CP_COMMIT() asm volatile("cp.async.commit_group;")
#define CP_WAIT0()  asm volatile("cp.async.wait_group 0;" ::: "memory")

// split 8 consecutive floats into bf16 hi + bf16 lo(residual), packed uint4
__device__ __forceinline__ void bf16_split8(const float* f, uint4& hi, uint4& lo) {
    unsigned h[4], l[4];
    #pragma unroll
    for (int i = 0; i < 4; i++) {
        float a = f[2 * i], b = f[2 * i + 1];
        __nv_bfloat16 ha = __float2bfloat16(a);
        __nv_bfloat16 hb = __float2bfloat16(b);
        __nv_bfloat162 hp; hp.x = ha; hp.y = hb;
        h[i] = *reinterpret_cast<unsigned*>(&hp);
        __nv_bfloat162 lp;
        lp.x = __float2bfloat16(a - __bfloat162float(ha));
        lp.y = __float2bfloat16(b - __bfloat162float(hb));
        l[i] = *reinterpret_cast<unsigned*>(&lp);
    }
    hi = make_uint4(h[0], h[1], h[2], h[3]);
    lo = make_uint4(l[0], l[1], l[2], l[3]);
}

// split 4 floats (float4) into hi/lo bf16 pairs packed as uint2 each
__device__ __forceinline__ void bf16_split4(float4 o, uint2& hi, uint2& lo) {
    unsigned h[2], l[2];
    float a[4] = {o.x, o.y, o.z, o.w};
    #pragma unroll
    for (int i = 0; i < 2; i++) {
        __nv_bfloat16 ha = __float2bfloat16(a[2 * i]);
        __nv_bfloat16 hb = __float2bfloat16(a[2 * i + 1]);
        __nv_bfloat162 hp; hp.x = ha; hp.y = hb;
        h[i] = *reinterpret_cast<unsigned*>(&hp);
        __nv_bfloat162 lp;
        lp.x = __float2bfloat16(a[2 * i] - __bfloat162float(ha));
        lp.y = __float2bfloat16(a[2 * i + 1] - __bfloat162float(hb));
        l[i] = *reinterpret_cast<unsigned*>(&lp);
    }
    hi = make_uint2(h[0], h[1]);
    lo = make_uint2(l[0], l[1]);
}

#define LDSM4(r0, r1, r2, r3, addr) \
    asm volatile("ldmatrix.sync.aligned.m8n8.x4.shared.b16 {%0,%1,%2,%3}, [%4];" \
                 : "=r"(r0), "=r"(r1), "=r"(r2), "=r"(r3) : "r"(addr))

#define MMA16816(d, a, b0, b1) \
    asm volatile("mma.sync.aligned.m16n8k16.row.col.f32.bf16.bf16.f32 " \
                 "{%0,%1,%2,%3}, {%4,%5,%6,%7}, {%8,%9}, {%0,%1,%2,%3};" \
                 : "+f"((d)[0]), "+f"((d)[1]), "+f"((d)[2]), "+f"((d)[3]) \
                 : "r"((a)[0]), "r"((a)[1]), "r"((a)[2]), "r"((a)[3]), \
                   "r"(b0), "r"(b1))

// ------------- dtype detect (int32 vs int64), 1 block -------------
__global__ void k_detect(const int* __restrict__ e32) {
    __shared__ int nz;
    if (threadIdx.x == 0) nz = 0;
    __syncthreads();
    for (int i = threadIdx.x; i < 1024; i += blockDim.x)
        if (e32[2 * i + 1] != 0) nz = 1;
    __syncthreads();
    if (threadIdx.x == 0) g_is64 = (nz == 0) ? 1 : 0;
}

// ------------- layer-0 input: fp32 x -> hi/lo bf16 planes -------------
__global__ void k_x2hilo(const float* __restrict__ x) {
    int t = blockIdx.x * blockDim.x + threadIdx.x;     // chunk of 8 elements
    if (t >= N_NODES * D_MODEL / 8) return;
    float f[8];
    *(float4*)(f)     = *(const float4*)(x + t * 8);
    *(float4*)(f + 4) = *(const float4*)(x + t * 8 + 4);
    uint4 hi, lo;
    bf16_split8(f, hi, lo);
    ((uint4*)g_Ahi)[t] = hi;
    ((uint4*)g_Alo)[t] = lo;
}

__global__ void k_extract(const int* __restrict__ e32) {
    int t = blockIdx.x * blockDim.x + threadIdx.x;
    if (t >= E_TOT) return;
    int s, d;
    if (t < N_EDGES) {
        if (g_is64) { s = e32[2 * t]; d = e32[2 * (N_EDGES + t)]; }
        else        { s = e32[t];     d = e32[N_EDGES + t]; }
    } else {
        s = t - N_EDGES; d = s;
    }
    g_src[t] = s;
    g_dst[t] = d;
    atomicAdd(&g_cnt[d], 1);
}

// exclusive scan; re-zeros g_cnt (invariant for graph replays)
__global__ void __launch_bounds__(1024) k_scan() {
    __shared__ int warpsum[32];
    const int t    = threadIdx.x;
    const int lane = t & 31;
    const int warp = t >> 5;
    const int base = t * 10;

    int local[10];
    int sum = 0;
    #pragma unroll
    for (int i = 0; i < 10; i++) {
        int idx = base + i;
        local[i] = (idx < N_NODES) ? g_cnt[idx] : 0;
        if (idx < N_NODES) g_cnt[idx] = 0;
        sum += local[i];
    }
    int incl = sum;
    #pragma unroll
    for (int off = 1; off < 32; off <<= 1) {
        int v = __shfl_up_sync(0xffffffffu, incl, off);
        if (lane >= off) incl += v;
    }
    if (lane == 31) warpsum[warp] = incl;
    __syncthreads();
    if (warp == 0) {
        int w = warpsum[lane];
        int wi = w;
        #pragma unroll
        for (int off = 1; off < 32; off <<= 1) {
            int v = __shfl_up_sync(0xffffffffu, wi, off);
            if (lane >= off) wi += v;
        }
        warpsum[lane] = wi - w;
    }
    __syncthreads();
    int run = warpsum[warp] + (incl - sum);
    #pragma unroll
    for (int i = 0; i < 10; i++) {
        int idx = base + i;
        if (idx < N_NODES) {
            g_start[idx]  = run;
            g_cursor[idx] = run;
        }
        run += local[i];
    }
    if (t == 0) g_start[N_NODES] = E_TOT;
}

__global__ void k_scatter() {
    int t = blockIdx.x * blockDim.x + threadIdx.x;
    if (t >= E_TOT) return;
    int d = g_dst[t];
    int pos = atomicAdd(&g_cursor[d], 1);
    g_csr[pos] = g_src[t];
}

// ---------------- W prep: W[k][n] fp32 -> Wt[n][k] bf16 hi/lo -------------
__global__ void __launch_bounds__(256) k_prep(
    const float* __restrict__ Wl, const float* __restrict__ Wr)
{
    __shared__ float sw[32][129];
    const int l    = blockIdx.x >> 1;
    const int side = blockIdx.x & 1;
    const float* W = (side ? Wr : Wl) + l * D_MODEL * D_MODEL;
    unsigned char* gH = g_Bt + (size_t)blockIdx.x * 65536;
    unsigned char* gL = gH + 32768;
    const int tid = threadIdx.x;

    for (int k0 = 0; k0 < 128; k0 += 32) {
        for (int i = tid; i < 32 * 128; i += 256) {
            int k = i >> 7, n = i & 127;
            sw[k][n] = W[(k0 + k) * 128 + n];
        }
        __syncthreads();
        const int n  = tid >> 1;
        const int kh = (tid & 1) * 16;
        #pragma unroll
        for (int half = 0; half < 2; half++) {
            int kk = kh + half * 8;
            float f[8];
            #pragma unroll
            for (int j = 0; j < 8; j++) f[j] = sw[kk + j][n];
            uint4 hi, lo;
            bf16_split8(f, hi, lo);
            *(uint4*)(gH + n * 256 + (k0 + kk) * 2) = hi;
            *(uint4*)(gL + n * 256 + (k0 + kk) * 2) = lo;
        }
        __syncthreads();
    }
}

// ---------------- tensor-core GEMM: out = A @ W + b (per side) -----------
// A read directly from bf16 hi/lo planes via cp.async (no conversion!).
// 64x128 block tile, 8 warps, K=128, bf16 3-pass split, fp32 accum.
__global__ void __launch_bounds__(256, 2) k_gemm(
    const unsigned char* __restrict__ gB_layer,
    const float* __restrict__ bl, const float* __restrict__ br)
{
    extern __shared__ char dsm[];
    char* Ahi = dsm;
    char* Alo = dsm + A_BYTES;
    char* Bhi = dsm + 2 * A_BYTES;
    char* Blo = dsm + 2 * A_BYTES + B_BYTES;

    const int tid  = threadIdx.x;
    const int warp = tid >> 5;
    const int lane = tid & 31;
    const int side = blockIdx.y;
    const int row0 = blockIdx.x * TILE_M;

    const unsigned char* gB = gB_layer + side * 65536;
    const float* bias = side ? br : bl;
    float* out = side ? g_xr : g_xl;

    // A copy: hi+lo planes, 64 rows x 16 chunks each = 2048 chunks, 8/thread
    {
        const unsigned ah = smem_u32(Ahi);
        const unsigned al = smem_u32(Alo);
        const unsigned char* gAh = (const unsigned char*)g_Ahi;
        const unsigned char* gAl = (const unsigned char*)g_Alo;
        #pragma unroll
        for (int i = 0; i < 8; i++) {
            int c   = tid + i * 256;
            int sel = c >> 10;            // 0: hi, 1: lo
            int cc  = c & 1023;
            int r   = cc >> 4;
            int ch  = cc & 15;
            int gr  = row0 + r;
            if (gr >= N_NODES) gr = N_NODES - 1;   // clamp; rows unstored later
            unsigned dst = (sel ? al : ah) + r * AROW + ch * 16;
            const unsigned char* src = (sel ? gAl : gAh) + gr * 256 + ch * 16;
            cp16(dst, src);
        }
    }
    // B copy: hi+lo, 128 rows x 16 chunks each = 4096 chunks, 16/thread
    {
        const unsigned bh = smem_u32(Bhi);
        const unsigned blo = smem_u32(Blo);
        #pragma unroll
        for (int i = 0; i < 16; i++) {
            int c   = tid + i * 256;
            int sel = c >> 11;
            int cc  = c & 2047;
            int r   = cc >> 4;
            int ch  = cc & 15;
            unsigned dst = (sel ? blo : bh) + r * AROW + ch * 16;
            cp16(dst, gB + sel * 32768 + r * 256 + ch * 16);
        }
        CP_COMMIT();
    }
    CP_WAIT0();
    __syncthreads();

    const int wm = warp >> 2;     // 0..1 -> m offset wm*32
    const int wn = warp & 3;      // 0..3 -> n offset wn*32

    float acc[2][4][4];
    #pragma unroll
    for (int mt = 0; mt < 2; mt++)
        #pragma unroll
        for (int nt = 0; nt < 4; nt++)
            #pragma unroll
            for (int q = 0; q < 4; q++) acc[mt][nt][q] = 0.0f;

    const unsigned laneOff = (lane & 15) * AROW + (lane >> 4) * 16;
    const unsigned aHiBase = smem_u32(Ahi) + wm * 32 * AROW + laneOff;
    const unsigned aLoBase = smem_u32(Alo) + wm * 32 * AROW + laneOff;
    const unsigned bHiBase = smem_u32(Bhi) + wn * 32 * AROW + laneOff;
    const unsigned bLoBase = smem_u32(Blo) + wn * 32 * AROW + laneOff;

    #pragma unroll 1
    for (int pass = 0; pass < 3; pass++) {
        const unsigned aBase = (pass == 1) ? aLoBase : aHiBase;
        const unsigned bBase = (pass == 2) ? bLoBase : bHiBase;
        #pragma unroll
        for (int kc = 0; kc < 8; kc++) {
            const unsigned kb = kc * 32;             // 16 halfs = 32 bytes
            unsigned A0[4], A1[4], B0[4], B1[4];
            LDSM4(A0[0], A0[1], A0[2], A0[3], aBase + kb);
            LDSM4(A1[0], A1[1], A1[2], A1[3], aBase + kb + 16 * AROW);
            LDSM4(B0[0], B0[1], B0[2], B0[3], bBase + kb);
            LDSM4(B1[0], B1[1], B1[2], B1[3], bBase + kb + 16 * AROW);
            MMA16816(acc[0][0], A0, B0[0], B0[2]);
            MMA16816(acc[0][1], A0, B0[1], B0[3]);
            MMA16816(acc[0][2], A0, B1[0], B1[2]);
            MMA16816(acc[0][3], A0, B1[1], B1[3]);
            MMA16816(acc[1][0], A1, B0[0], B0[2]);
            MMA16816(acc[1][1], A1, B0[1], B0[3]);
            MMA16816(acc[1][2], A1, B1[0], B1[2]);
            MMA16816(acc[1][3], A1, B1[1], B1[3]);
        }
    }

    // epilogue: c-fragment rows (lane>>2, +8), cols (lane&3)*2, +1
    #pragma unroll
    for (int mt = 0; mt < 2; mt++) {
        const int rbase = row0 + wm * 32 + mt * 16 + (lane >> 2);
        #pragma unroll
        for (int nt = 0; nt < 4; nt++) {
            const int col = wn * 32 + nt * 8 + (lane & 3) * 2;
            const float b0 = bias[col], b1 = bias[col + 1];
            if (rbase < N_NODES) {
                float2 o; o.x = acc[mt][nt][0] + b0; o.y = acc[mt][nt][1] + b1;
                *(float2*)(out + rbase * 128 + col) = o;
            }
            if (rbase + 8 < N_NODES) {
                float2 o; o.x = acc[mt][nt][2] + b0; o.y = acc[mt][nt][3] + b1;
                *(float2*)(out + (rbase + 8) * 128 + col) = o;
            }
        }
    }
}

// ---------------- fused edge kernel: NO-MAX softmax + aggregate ----------
// output written directly as bf16 hi/lo planes (next GEMM's A input)
__global__ void __launch_bounds__(256) k_layer(
    const float* __restrict__ att, const float* __restrict__ bias)
{
    const int warp = threadIdx.x >> 5;
    const int n    = blockIdx.x * 8 + warp;
    if (n >= N_NODES) return;
    const int lane = threadIdx.x & 31;
    const int c    = lane * 4;

    const float4 xr = *(const float4*)(g_xr + n * 128 + c);
    const float4 av = *(const float4*)(att + c);

    const int beg = g_start[n];
    const int end = g_start[n + 1];

    float  s = 0.0f;
    float4 acc = make_float4(0.f, 0.f, 0.f, 0.f);

    float4 v0 = *(const float4*)(g_xl + g_csr[beg] * 128 + c);
    float4 v1 = (beg + 1 < end)
        ? *(const float4*)(g_xl + g_csr[beg + 1] * 128 + c) : v0;

    for (int e = beg; e < end; e++) {
        float4 cur = v0;
        v0 = v1;
        if (e + 2 < end)
            v1 = *(const float4*)(g_xl + g_csr[e + 2] * 128 + c);

        float zx = cur.x + xr.x; zx = fmaxf(zx, NEG_SLOPE * zx);
        float zy = cur.y + xr.y; zy = fmaxf(zy, NEG_SLOPE * zy);
        float zz = cur.z + xr.z; zz = fmaxf(zz, NEG_SLOPE * zz);
        float zw = cur.w + xr.w; zw = fmaxf(zw, NEG_SLOPE * zw);
        float w = zx * av.x;
        w = fmaf(zy, av.y, w);
        w = fmaf(zz, av.z, w);
        w = fmaf(zw, av.w, w);
        w += __shfl_xor_sync(0xffffffffu, w, 1);
        w += __shfl_xor_sync(0xffffffffu, w, 2);

        float p = __expf(w);
        s += p;
        acc.x = fmaf(p, cur.x, acc.x);
        acc.y = fmaf(p, cur.y, acc.y);
        acc.z = fmaf(p, cur.z, acc.z);
        acc.w = fmaf(p, cur.w, acc.w);
    }

    const float inv = 1.0f / (s + 1e-16f);
    const float4 bi = *(const float4*)(bias + c);
    float4 o;
    o.x = acc.x * inv + bi.x;
    o.y = acc.y * inv + bi.y;
    o.z = acc.z * inv + bi.z;
    o.w = acc.w * inv + bi.w;

    uint2 hi, lo;
    bf16_split4(o, hi, lo);
    *(uint2*)(g_Ahi + n * 128 + c) = hi;
    *(uint2*)(g_Alo + n * 128 + c) = lo;
}

// ---------------- final head (reads hi/lo planes) ----------------
__global__ void k_head(const float* __restrict__ w,
                       const float* __restrict__ bh, float* __restrict__ out)
{
    int gt   = blockIdx.x * blockDim.x + threadIdx.x;
    int warp = gt >> 5;
    int lane = gt & 31;
    if (warp >= (N_NODES / CHUNK) * NUM_LABELS) return;
    int c = warp / NUM_LABELS;
    int l = warp % NUM_LABELS;
    const int row = (c * CHUNK + l) * 128;
    float s = 0.0f;
    #pragma unroll
    for (int i = lane; i < 128; i += 32) {
        __nv_bfloat16 h = *(const __nv_bfloat16*)(g_Ahi + row + i);
        __nv_bfloat16 lo = *(const __nv_bfloat16*)(g_Alo + row + i);
        float v = __bfloat162float(h) + __bfloat162float(lo);
        s = fmaf(v, w[i], s);
    }
    #pragma unroll
    for (int o = 16; o; o >>= 1) s += __shfl_down_sync(0xffffffffu, s, o);
    if (lane == 0) out[warp] = s + bh[0];
}

// ---------------- launch ----------------
extern "C" void kernel_launch(void* const* d_in, const int* in_sizes, int n_in,
                              void* d_out, int out_size)
{
    const float* x    = (const float*)d_in[0];
    const int*   eidx = (const int*)  d_in[1];
    // d_in[2] = nchunks (fixed = 8 -> CHUNK = 10)
    const float* Wl   = (const float*)d_in[3];
    const float* bl   = (const float*)d_in[4];
    const float* Wr   = (const float*)d_in[5];
    const float* br   = (const float*)d_in[6];
    const float* att  = (const float*)d_in[7];
    const float* bias = (const float*)d_in[8];
    const float* wh   = (const float*)d_in[9];
    const float* bh   = (const float*)d_in[10];
    float* out = (float*)d_out;

    cudaFuncSetAttribute(k_gemm, cudaFuncAttributeMaxDynamicSharedMemorySize,
                         GEMM_SMEM);

    unsigned char* gBt = nullptr;
    cudaGetSymbolAddress((void**)&gBt, g_Bt);

    dim3 gg(GEMM_GX, 2);
    const int layer_grid = (N_NODES + 7) / 8;

    // profiled slot #4 = k_gemm (layer 0)
    k_detect<<<1, 256>>>(eidx);                                   // 1
    k_x2hilo<<<(N_NODES * D_MODEL / 8 + 255) / 256, 256>>>(x);    // 2
    k_prep<<<NUM_LAYERS * 2, 256>>>(Wl, Wr);                      // 3
    k_gemm<<<gg, 256, GEMM_SMEM>>>(gBt, bl, br);                  // 4 <-- profiled
    k_extract<<<(E_TOT + 255) / 256, 256>>>(eidx);                // 5
    k_scan<<<1, 1024>>>();                                        // 6
    k_scatter<<<(E_TOT + 255) / 256, 256>>>();                    // 7
    k_layer<<<layer_grid, 256>>>(att, bias);                      // 8

    for (int l = 1; l < NUM_LAYERS; l++) {
        k_gemm<<<gg, 256, GEMM_SMEM>>>(gBt + (size_t)l * 131072,
                                       bl + l * D_MODEL, br + l * D_MODEL);
        k_layer<<<layer_grid, 256>>>(att + l * NHEAD * HEAD_DIM,
                                     bias + l * D_MODEL);
    }
    int nwarp = (N_NODES / CHUNK) * NUM_LABELS;
    k_head<<<(nwarp * 32 + 255) / 256, 256>>>(wh, bh, out);
}

// round 15
// speedup vs baseline: 1.6203x; 1.0459x over previous
#include <cuda_runtime.h>
#include <cuda_bf16.h>
#include <cstdint>

#define N_NODES   10000
#define N_EDGES   160000
#define E_TOT     170000
#define D_MODEL   128
#define NHEAD     8
#define HEAD_DIM  16
#define NUM_LAYERS 7
#define CHUNK     10
#define NUM_LABELS 2
#define NEG_SLOPE 0.2f

// GEMM geometry
#define TILE_M    64
#define GEMM_GX   ((N_NODES + TILE_M - 1) / TILE_M)   // 157
#define AROW      272                                  // bf16 row stride (bytes)
#define A_BYTES   (TILE_M * AROW)                      // 17408 (one of hi/lo)
#define B_BYTES   (128 * AROW)                         // 34816 (one of hi/lo)
#define GEMM_SMEM (2 * A_BYTES + 2 * B_BYTES)          // 104448

// ---------------- device scratch ----------------
__device__ float g_xl[N_NODES * D_MODEL];
__device__ float g_xr[N_NODES * D_MODEL];
// activations in bf16 hi/lo planes (current layer input)
__device__ __align__(16) unsigned short g_Ahi[N_NODES * D_MODEL];
__device__ __align__(16) unsigned short g_Alo[N_NODES * D_MODEL];
__device__ int   g_src[E_TOT];
__device__ int   g_dst[E_TOT];
__device__ int   g_cnt[N_NODES];          // zero-init; k_scan re-zeros each run
__device__ int   g_start[N_NODES + 1];
__device__ int   g_cursor[N_NODES];
__device__ int   g_csr[E_TOT];
__device__ int   g_is64;
// W^T bf16 hi/lo: [layer][side][hi 32KB | lo 32KB], rows n (128), cols k (128)
__device__ __align__(16) unsigned char g_Bt[NUM_LAYERS * 2 * 65536];

// ---------------- helpers ----------------
__device__ __forceinline__ unsigned smem_u32(const void* p) {
    unsigned a;
    asm("{ .reg .u64 t; cvta.to.shared.u64 t, %1; cvt.u32.u64 %0, t; }"
        : "=r"(a) : "l"(p));
    return a;
}
__device__ __forceinline__ void cp16(unsigned s, const void* g) {
    asm volatile("cp.async.ca.shared.global [%0], [%1], 16;" :: "r"(s), "l"(g));
}
#define CP_COMMIT() asm volatile("cp.async.commit_group;")

// split 8 consecutive floats into bf16 hi + bf16 lo(residual), packed uint4
__device__ __forceinline__ void bf16_split8(const float* f, uint4& hi, uint4& lo) {
    unsigned h[4], l[4];
    #pragma unroll
    for (int i = 0; i < 4; i++) {
        float a = f[2 * i], b = f[2 * i + 1];
        __nv_bfloat16 ha = __float2bfloat16(a);
        __nv_bfloat16 hb = __float2bfloat16(b);
        __nv_bfloat162 hp; hp.x = ha; hp.y = hb;
        h[i] = *reinterpret_cast<unsigned*>(&hp);
        __nv_bfloat162 lp;
        lp.x = __float2bfloat16(a - __bfloat162float(ha));
        lp.y = __float2bfloat16(b - __bfloat162float(hb));
        l[i] = *reinterpret_cast<unsigned*>(&lp);
    }
    hi = make_uint4(h[0], h[1], h[2], h[3]);
    lo = make_uint4(l[0], l[1], l[2], l[3]);
}

// split 4 floats (float4) into hi/lo bf16 pairs packed as uint2 each
__device__ __forceinline__ void bf16_split4(float4 o, uint2& hi, uint2& lo) {
    unsigned h[2], l[2];
    float a[4] = {o.x, o.y, o.z, o.w};
    #pragma unroll
    for (int i = 0; i < 2; i++) {
        __nv_bfloat16 ha = __float2bfloat16(a[2 * i]);
        __nv_bfloat16 hb = __float2bfloat16(a[2 * i + 1]);
        __nv_bfloat162 hp; hp.x = ha; hp.y = hb;
        h[i] = *reinterpret_cast<unsigned*>(&hp);
        __nv_bfloat162 lp;
        lp.x = __float2bfloat16(a[2 * i] - __bfloat162float(ha));
        lp.y = __float2bfloat16(a[2 * i + 1] - __bfloat162float(hb));
        l[i] = *reinterpret_cast<unsigned*>(&lp);
    }
    hi = make_uint2(h[0], h[1]);
    lo = make_uint2(l[0], l[1]);
}

#define LDSM4(r0, r1, r2, r3, addr) \
    asm volatile("ldmatrix.sync.aligned.m8n8.x4.shared.b16 {%0,%1,%2,%3}, [%4];" \
                 : "=r"(r0), "=r"(r1), "=r"(r2), "=r"(r3) : "r"(addr))

#define MMA16816(d, a, b0, b1) \
    asm volatile("mma.sync.aligned.m16n8k16.row.col.f32.bf16.bf16.f32 " \
                 "{%0,%1,%2,%3}, {%4,%5,%6,%7}, {%8,%9}, {%0,%1,%2,%3};" \
                 : "+f"((d)[0]), "+f"((d)[1]), "+f"((d)[2]), "+f"((d)[3]) \
                 : "r"((a)[0]), "r"((a)[1]), "r"((a)[2]), "r"((a)[3]), \
                   "r"(b0), "r"(b1))

// ------------- dtype detect (int32 vs int64), 1 block -------------
__global__ void k_detect(const int* __restrict__ e32) {
    __shared__ int nz;
    if (threadIdx.x == 0) nz = 0;
    __syncthreads();
    for (int i = threadIdx.x; i < 1024; i += blockDim.x)
        if (e32[2 * i + 1] != 0) nz = 1;
    __syncthreads();
    if (threadIdx.x == 0) g_is64 = (nz == 0) ? 1 : 0;
}

// ------------- layer-0 input: fp32 x -> hi/lo bf16 planes -------------
__global__ void k_x2hilo(const float* __restrict__ x) {
    int t = blockIdx.x * blockDim.x + threadIdx.x;     // chunk of 8 elements
    if (t >= N_NODES * D_MODEL / 8) return;
    float f[8];
    *(float4*)(f)     = *(const float4*)(x + t * 8);
    *(float4*)(f + 4) = *(const float4*)(x + t * 8 + 4);
    uint4 hi, lo;
    bf16_split8(f, hi, lo);
    ((uint4*)g_Ahi)[t] = hi;
    ((uint4*)g_Alo)[t] = lo;
}

__global__ void k_extract(const int* __restrict__ e32) {
    int t = blockIdx.x * blockDim.x + threadIdx.x;
    if (t >= E_TOT) return;
    int s, d;
    if (t < N_EDGES) {
        if (g_is64) { s = e32[2 * t]; d = e32[2 * (N_EDGES + t)]; }
        else        { s = e32[t];     d = e32[N_EDGES + t]; }
    } else {
        s = t - N_EDGES; d = s;
    }
    g_src[t] = s;
    g_dst[t] = d;
    atomicAdd(&g_cnt[d], 1);
}

// exclusive scan; re-zeros g_cnt (invariant for graph replays)
__global__ void __launch_bounds__(1024) k_scan() {
    __shared__ int warpsum[32];
    const int t    = threadIdx.x;
    const int lane = t & 31;
    const int warp = t >> 5;
    const int base = t * 10;

    int local[10];
    int sum = 0;
    #pragma unroll
    for (int i = 0; i < 10; i++) {
        int idx = base + i;
        local[i] = (idx < N_NODES) ? g_cnt[idx] : 0;
        if (idx < N_NODES) g_cnt[idx] = 0;
        sum += local[i];
    }
    int incl = sum;
    #pragma unroll
    for (int off = 1; off < 32; off <<= 1) {
        int v = __shfl_up_sync(0xffffffffu, incl, off);
        if (lane >= off) incl += v;
    }
    if (lane == 31) warpsum[warp] = incl;
    __syncthreads();
    if (warp == 0) {
        int w = warpsum[lane];
        int wi = w;
        #pragma unroll
        for (int off = 1; off < 32; off <<= 1) {
            int v = __shfl_up_sync(0xffffffffu, wi, off);
            if (lane >= off) wi += v;
        }
        warpsum[lane] = wi - w;
    }
    __syncthreads();
    int run = warpsum[warp] + (incl - sum);
    #pragma unroll
    for (int i = 0; i < 10; i++) {
        int idx = base + i;
        if (idx < N_NODES) {
            g_start[idx]  = run;
            g_cursor[idx] = run;
        }
        run += local[i];
    }
    if (t == 0) g_start[N_NODES] = E_TOT;
}

__global__ void k_scatter() {
    int t = blockIdx.x * blockDim.x + threadIdx.x;
    if (t >= E_TOT) return;
    int d = g_dst[t];
    int pos = atomicAdd(&g_cursor[d], 1);
    g_csr[pos] = g_src[t];
}

// ---------------- W prep: W[k][n] fp32 -> Wt[n][k] bf16 hi/lo -------------
__global__ void __launch_bounds__(256) k_prep(
    const float* __restrict__ Wl, const float* __restrict__ Wr)
{
    __shared__ float sw[32][129];
    const int l    = blockIdx.x >> 1;
    const int side = blockIdx.x & 1;
    const float* W = (side ? Wr : Wl) + l * D_MODEL * D_MODEL;
    unsigned char* gH = g_Bt + (size_t)blockIdx.x * 65536;
    unsigned char* gL = gH + 32768;
    const int tid = threadIdx.x;

    for (int k0 = 0; k0 < 128; k0 += 32) {
        for (int i = tid; i < 32 * 128; i += 256) {
            int k = i >> 7, n = i & 127;
            sw[k][n] = W[(k0 + k) * 128 + n];
        }
        __syncthreads();
        const int n  = tid >> 1;
        const int kh = (tid & 1) * 16;
        #pragma unroll
        for (int half = 0; half < 2; half++) {
            int kk = kh + half * 8;
            float f[8];
            #pragma unroll
            for (int j = 0; j < 8; j++) f[j] = sw[kk + j][n];
            uint4 hi, lo;
            bf16_split8(f, hi, lo);
            *(uint4*)(gH + n * 256 + (k0 + kk) * 2) = hi;
            *(uint4*)(gL + n * 256 + (k0 + kk) * 2) = lo;
        }
        __syncthreads();
    }
}

// ---------------- tensor-core GEMM: out = A @ W + b (per side) -----------
// Split-group cp.async pipeline: hi tiles (group committed first) feed pass 1
// while lo tiles are still in flight; passes 2-3 after wait_group 0.
__global__ void __launch_bounds__(256, 2) k_gemm(
    const unsigned char* __restrict__ gB_layer,
    const float* __restrict__ bl, const float* __restrict__ br)
{
    extern __shared__ char dsm[];
    char* Ahi = dsm;
    char* Alo = dsm + A_BYTES;
    char* Bhi = dsm + 2 * A_BYTES;
    char* Blo = dsm + 2 * A_BYTES + B_BYTES;

    const int tid  = threadIdx.x;
    const int warp = tid >> 5;
    const int lane = tid & 31;
    const int side = blockIdx.y;
    const int row0 = blockIdx.x * TILE_M;

    const unsigned char* gB = gB_layer + side * 65536;
    const float* bias = side ? br : bl;
    float* out = side ? g_xr : g_xl;

    const unsigned ah = smem_u32(Ahi);
    const unsigned al = smem_u32(Alo);
    const unsigned bh = smem_u32(Bhi);
    const unsigned blo = smem_u32(Blo);
    const unsigned char* gAh = (const unsigned char*)g_Ahi;
    const unsigned char* gAl = (const unsigned char*)g_Alo;

    // ---- group HI: A_hi (1024 chunks) + B_hi (2048 chunks) ----
    #pragma unroll
    for (int i = 0; i < 4; i++) {
        int cc = tid + i * 256;
        int r  = cc >> 4;
        int ch = cc & 15;
        int gr = row0 + r;
        if (gr >= N_NODES) gr = N_NODES - 1;
        cp16(ah + r * AROW + ch * 16, gAh + gr * 256 + ch * 16);
    }
    #pragma unroll
    for (int i = 0; i < 8; i++) {
        int cc = tid + i * 256;
        int r  = cc >> 4;
        int ch = cc & 15;
        cp16(bh + r * AROW + ch * 16, gB + r * 256 + ch * 16);
    }
    CP_COMMIT();
    // ---- group LO: A_lo + B_lo ----
    #pragma unroll
    for (int i = 0; i < 4; i++) {
        int cc = tid + i * 256;
        int r  = cc >> 4;
        int ch = cc & 15;
        int gr = row0 + r;
        if (gr >= N_NODES) gr = N_NODES - 1;
        cp16(al + r * AROW + ch * 16, gAl + gr * 256 + ch * 16);
    }
    #pragma unroll
    for (int i = 0; i < 8; i++) {
        int cc = tid + i * 256;
        int r  = cc >> 4;
        int ch = cc & 15;
        cp16(blo + r * AROW + ch * 16, gB + 32768 + r * 256 + ch * 16);
    }
    CP_COMMIT();

    const int wm = warp >> 2;     // 0..1 -> m offset wm*32
    const int wn = warp & 3;      // 0..3 -> n offset wn*32

    float acc[2][4][4];
    #pragma unroll
    for (int mt = 0; mt < 2; mt++)
        #pragma unroll
        for (int nt = 0; nt < 4; nt++)
            #pragma unroll
            for (int q = 0; q < 4; q++) acc[mt][nt][q] = 0.0f;

    const unsigned laneOff = (lane & 15) * AROW + (lane >> 4) * 16;
    const unsigned aHiBase = ah + wm * 32 * AROW + laneOff;
    const unsigned aLoBase = al + wm * 32 * AROW + laneOff;
    const unsigned bHiBase = bh + wn * 32 * AROW + laneOff;
    const unsigned bLoBase = blo + wn * 32 * AROW + laneOff;

    // hi tiles ready -> start pass 1 while lo tiles are still in flight
    asm volatile("cp.async.wait_group 1;" ::: "memory");
    __syncthreads();

    #pragma unroll 1
    for (int pass = 0; pass < 3; pass++) {
        if (pass == 1) {
            asm volatile("cp.async.wait_group 0;" ::: "memory");
            __syncthreads();
        }
        const unsigned aBase = (pass == 1) ? aLoBase : aHiBase;
        const unsigned bBase = (pass == 2) ? bLoBase : bHiBase;
        #pragma unroll
        for (int kc = 0; kc < 8; kc++) {
            const unsigned kb = kc * 32;             // 16 halfs = 32 bytes
            unsigned A0[4], A1[4], B0[4], B1[4];
            LDSM4(A0[0], A0[1], A0[2], A0[3], aBase + kb);
            LDSM4(A1[0], A1[1], A1[2], A1[3], aBase + kb + 16 * AROW);
            LDSM4(B0[0], B0[1], B0[2], B0[3], bBase + kb);
            LDSM4(B1[0], B1[1], B1[2], B1[3], bBase + kb + 16 * AROW);
            MMA16816(acc[0][0], A0, B0[0], B0[2]);
            MMA16816(acc[0][1], A0, B0[1], B0[3]);
            MMA16816(acc[0][2], A0, B1[0], B1[2]);
            MMA16816(acc[0][3], A0, B1[1], B1[3]);
            MMA16816(acc[1][0], A1, B0[0], B0[2]);
            MMA16816(acc[1][1], A1, B0[1], B0[3]);
            MMA16816(acc[1][2], A1, B1[0], B1[2]);
            MMA16816(acc[1][3], A1, B1[1], B1[3]);
        }
    }

    // epilogue: c-fragment rows (lane>>2, +8), cols (lane&3)*2, +1
    #pragma unroll
    for (int mt = 0; mt < 2; mt++) {
        const int rbase = row0 + wm * 32 + mt * 16 + (lane >> 2);
        #pragma unroll
        for (int nt = 0; nt < 4; nt++) {
            const int col = wn * 32 + nt * 8 + (lane & 3) * 2;
            const float b0 = bias[col], b1 = bias[col + 1];
            if (rbase < N_NODES) {
                float2 o; o.x = acc[mt][nt][0] + b0; o.y = acc[mt][nt][1] + b1;
                *(float2*)(out + rbase * 128 + col) = o;
            }
            if (rbase + 8 < N_NODES) {
                float2 o; o.x = acc[mt][nt][2] + b0; o.y = acc[mt][nt][3] + b1;
                *(float2*)(out + (rbase + 8) * 128 + col) = o;
            }
        }
    }
}

// ---------------- fused edge kernel: NO-MAX softmax + aggregate ----------
// 4-deep branch-free prefetch ring on the gathered rows (MLP=4).
// output written directly as bf16 hi/lo planes (next GEMM's A input)
__global__ void __launch_bounds__(256) k_layer(
    const float* __restrict__ att, const float* __restrict__ bias)
{
    const int warp = threadIdx.x >> 5;
    const int n    = blockIdx.x * 8 + warp;
    if (n >= N_NODES) return;
    const int lane = threadIdx.x & 31;
    const int c    = lane * 4;

    const float4 xr = *(const float4*)(g_xr + n * 128 + c);
    const float4 av = *(const float4*)(att + c);

    const int beg  = g_start[n];
    const int end  = g_start[n + 1];
    const int last = end - 1;

    float  s = 0.0f;
    float4 acc = make_float4(0.f, 0.f, 0.f, 0.f);

    // 4-deep prefetch (clamped; redundant tail loads hit cache)
    int i1 = beg + 1 < last ? beg + 1 : last;
    int i2 = beg + 2 < last ? beg + 2 : last;
    int i3 = beg + 3 < last ? beg + 3 : last;
    float4 v0 = *(const float4*)(g_xl + g_csr[beg] * 128 + c);
    float4 v1 = *(const float4*)(g_xl + g_csr[i1]  * 128 + c);
    float4 v2 = *(const float4*)(g_xl + g_csr[i2]  * 128 + c);
    float4 v3 = *(const float4*)(g_xl + g_csr[i3]  * 128 + c);

    for (int e = beg; e < end; e++) {
        float4 cur = v0;
        v0 = v1; v1 = v2; v2 = v3;
        int nx = e + 4 < last ? e + 4 : last;
        v3 = *(const float4*)(g_xl + g_csr[nx] * 128 + c);

        float zx = cur.x + xr.x; zx = fmaxf(zx, NEG_SLOPE * zx);
        float zy = cur.y + xr.y; zy = fmaxf(zy, NEG_SLOPE * zy);
        float zz = cur.z + xr.z; zz = fmaxf(zz, NEG_SLOPE * zz);
        float zw = cur.w + xr.w; zw = fmaxf(zw, NEG_SLOPE * zw);
        float w = zx * av.x;
        w = fmaf(zy, av.y, w);
        w = fmaf(zz, av.z, w);
        w = fmaf(zw, av.w, w);
        w += __shfl_xor_sync(0xffffffffu, w, 1);
        w += __shfl_xor_sync(0xffffffffu, w, 2);

        float p = __expf(w);
        s += p;
        acc.x = fmaf(p, cur.x, acc.x);
        acc.y = fmaf(p, cur.y, acc.y);
        acc.z = fmaf(p, cur.z, acc.z);
        acc.w = fmaf(p, cur.w, acc.w);
    }

    const float inv = 1.0f / (s + 1e-16f);
    const float4 bi = *(const float4*)(bias + c);
    float4 o;
    o.x = acc.x * inv + bi.x;
    o.y = acc.y * inv + bi.y;
    o.z = acc.z * inv + bi.z;
    o.w = acc.w * inv + bi.w;

    uint2 hi, lo;
    bf16_split4(o, hi, lo);
    *(uint2*)(g_Ahi + n * 128 + c) = hi;
    *(uint2*)(g_Alo + n * 128 + c) = lo;
}

// ---------------- final head (reads hi/lo planes) ----------------
__global__ void k_head(const float* __restrict__ w,
                       const float* __restrict__ bh, float* __restrict__ out)
{
    int gt   = blockIdx.x * blockDim.x + threadIdx.x;
    int warp = gt >> 5;
    int lane = gt & 31;
    if (warp >= (N_NODES / CHUNK) * NUM_LABELS) return;
    int c = warp / NUM_LABELS;
    int l = warp % NUM_LABELS;
    const int row = (c * CHUNK + l) * 128;
    float s = 0.0f;
    #pragma unroll
    for (int i = lane; i < 128; i += 32) {
        __nv_bfloat16 h = *(const __nv_bfloat16*)(g_Ahi + row + i);
        __nv_bfloat16 lo = *(const __nv_bfloat16*)(g_Alo + row + i);
        float v = __bfloat162float(h) + __bfloat162float(lo);
        s = fmaf(v, w[i], s);
    }
    #pragma unroll
    for (int o = 16; o; o >>= 1) s += __shfl_down_sync(0xffffffffu, s, o);
    if (lane == 0) out[warp] = s + bh[0];
}

// ---------------- launch ----------------
extern "C" void kernel_launch(void* const* d_in, const int* in_sizes, int n_in,
                              void* d_out, int out_size)
{
    const float* x    = (const float*)d_in[0];
    const int*   eidx = (const int*)  d_in[1];
    // d_in[2] = nchunks (fixed = 8 -> CHUNK = 10)
    const float* Wl   = (const float*)d_in[3];
    const float* bl   = (const float*)d_in[4];
    const float* Wr   = (const float*)d_in[5];
    const float* br   = (const float*)d_in[6];
    const float* att  = (const float*)d_in[7];
    const float* bias = (const float*)d_in[8];
    const float* wh   = (const float*)d_in[9];
    const float* bh   = (const float*)d_in[10];
    float* out = (float*)d_out;

    cudaFuncSetAttribute(k_gemm, cudaFuncAttributeMaxDynamicSharedMemorySize,
                         GEMM_SMEM);

    unsigned char* gBt = nullptr;
    cudaGetSymbolAddress((void**)&gBt, g_Bt);

    dim3 gg(GEMM_GX, 2);
    const int layer_grid = (N_NODES + 7) / 8;

    // profiled slot #4 = k_gemm (layer 0)
    k_detect<<<1, 256>>>(eidx);                                   // 1
    k_x2hilo<<<(N_NODES * D_MODEL / 8 + 255) / 256, 256>>>(x);    // 2
    k_prep<<<NUM_LAYERS * 2, 256>>>(Wl, Wr);                      // 3
    k_gemm<<<gg, 256, GEMM_SMEM>>>(gBt, bl, br);                  // 4 <-- profiled
    k_extract<<<(E_TOT + 255) / 256, 256>>>(eidx);                // 5
    k_scan<<<1, 1024>>>();                                        // 6
    k_scatter<<<(E_TOT + 255) / 256, 256>>>();                    // 7
    k_layer<<<layer_grid, 256>>>(att, bias);                      // 8

    for (int l = 1; l < NUM_LAYERS; l++) {
        k_gemm<<<gg, 256, GEMM_SMEM>>>(gBt + (size_t)l * 131072,
                                       bl + l * D_MODEL, br + l * D_MODEL);
        k_layer<<<layer_grid, 256>>>(att + l * NHEAD * HEAD_DIM,
                                     bias + l * D_MODEL);
    }
    int nwarp = (N_NODES / CHUNK) * NUM_LABELS;
    k_head<<<(nwarp * 32 + 255) / 256, 256>>>(wh, bh, out);
}